// round 3
// baseline (speedup 1.0000x reference)
#include <cuda_runtime.h>
#include <math.h>

// ---------------- problem constants ----------------
// images: 400 total (100 support, 300 query), 3x84x84
// backbone: 3->64 (84->42) ->64 (42->21) ->128 (21->10) ->512 (10->5)
// outputs: predict_test (300x64) then cls_scores (300x5x5x5)

static const int N_IMG = 400;
static const int N_SUP = 100;

// ---------------- scratch (static device globals; no allocation) ----------------
__device__ float g_f1[400u * 64u * 42u * 42u];    // ~180 MB
__device__ float g_f2[400u * 64u * 21u * 21u];    // ~45 MB
__device__ float g_f3[400u * 128u * 10u * 10u];   // ~20 MB
__device__ float g_f4[400u * 512u * 5u * 5u];     // ~20 MB
__device__ float g_fa[4u * 5u * 512u];            // normalized class prototypes

// duplicated-weight buffers, layout [ci*9+k][co] with each value stored {w,w}
__device__ float g_w1d[3u   * 9u * 64u  * 2u];
__device__ float g_w2d[64u  * 9u * 64u  * 2u];
__device__ float g_w3d[64u  * 9u * 128u * 2u];
__device__ float g_w4d[128u * 9u * 512u * 2u];

// ---------------- packed f32x2 FMA (Blackwell FFMA2; ptxas never auto-emits) ----
typedef unsigned long long u64_t;
__device__ __forceinline__ float2 fma2(float2 a, float2 b, float2 c) {
    float2 d;
    asm("fma.rn.f32x2 %0, %1, %2, %3;"
        : "=l"(*reinterpret_cast<u64_t*>(&d))
        : "l"(*reinterpret_cast<const u64_t*>(&a)),
          "l"(*reinterpret_cast<const u64_t*>(&b)),
          "l"(*reinterpret_cast<const u64_t*>(&c)));
    return d;
}

// ---------------- weight repack: [co][ci][3][3] -> [ci*9+k][co] duplicated ----
__global__ void repack_kernel(const float* __restrict__ w, float* __restrict__ outdup,
                              int cin, int cout)
{
    const int total = cin * 9 * cout;
    for (int idx = blockIdx.x * blockDim.x + threadIdx.x; idx < total;
         idx += gridDim.x * blockDim.x) {
        const int co  = idx % cout;
        const int rem = idx / cout;           // ci*9 + k
        const float v = w[(size_t)co * cin * 9 + rem];
        outdup[2 * (size_t)idx]     = v;
        outdup[2 * (size_t)idx + 1] = v;
    }
}

// ---------------- fused conv3x3(SAME) + bias + relu + maxpool2x2, f32x2 path ----
// tid = cog*SPAD + s. Each thread: COPT output channels x (2x2 pre-pool pixels),
// horizontal pixel pairs packed into f32x2 accumulators.
// Weights staged as duplicated pairs {w,w}: LDS.128 = 2 packed weights, broadcast.
template<int CIN, int CINC, int COUT, int COCTA, int COPT,
         int HIN, int WIN, int HPO, int WPO, int TY, int TX, int SPAD>
__global__ void __launch_bounds__(SPAD*(COCTA/COPT))
conv_pool_kernel(const float* __restrict__ inA, const float* __restrict__ inB, int nsplit,
                 const float* __restrict__ wdup, const float* __restrict__ bias,
                 float* __restrict__ out)
{
    constexpr int PH  = 2*TY + 2;
    constexpr int PW  = 2*TX + 2;               // even -> float2 alignment holds
    constexpr int COG = COCTA / COPT;
    constexpr int NT  = SPAD * COG;
    constexpr int TILESX = (WPO + TX - 1) / TX;
    constexpr int IN_FLOATS = CINC * PH * PW;
    constexpr int W_ROWS    = CINC * 9;          // rows of duplicated weights per chunk
    constexpr int W_F4_PER_ROW = COCTA / 2;      // float4s per row (COCTA float2s)

    extern __shared__ __align__(16) float smem[];
    float* s_in = smem;                          // IN_FLOATS
    float* s_w  = smem + IN_FLOATS;              // W_ROWS * COCTA * 2 floats

    const int n     = blockIdx.z;
    const int cob   = blockIdx.y * COCTA;
    const int tileY = blockIdx.x / TILESX;
    const int tileX = blockIdx.x % TILESX;
    const int tid   = threadIdx.x;
    const int s     = tid % SPAD;
    const int cog   = tid / SPAD;
    const bool act  = (s < TY * TX);
    const int yl    = act ? (s / TX) : 0;
    const int xl    = act ? (s % TX) : 0;

    const int oy = 2 * (tileY * TY) - 1;         // input-patch origin (SAME padding)
    const int ox = 2 * (tileX * TX) - 1;

    const float* img = (n < nsplit)
        ? inA + (size_t)n * CIN * HIN * WIN
        : inB + (size_t)(n - nsplit) * CIN * HIN * WIN;

    float2 accT[COPT], accB[COPT];               // (row0 c0,c1) / (row1 c0,c1)
    #pragma unroll
    for (int j = 0; j < COPT; j++) {
        accT[j] = make_float2(0.f, 0.f);
        accB[j] = make_float2(0.f, 0.f);
    }

    for (int cib = 0; cib < CIN; cib += CINC) {
        __syncthreads();
        // ---- input patch (zero-padded) ----
        for (int idx = tid; idx < IN_FLOATS; idx += NT) {
            int ci  = idx / (PH * PW);
            int rem = idx - ci * (PH * PW);
            int r   = rem / PW;
            int cl  = rem - r * PW;
            int gy  = oy + r, gx = ox + cl;
            float v = 0.f;
            if (gy >= 0 && gy < HIN && gx >= 0 && gx < WIN)
                v = img[((size_t)(cib + ci) * HIN + gy) * WIN + gx];
            s_in[idx] = v;
        }
        // ---- weights: contiguous duplicated rows, coalesced float4 copies ----
        {
            const float4* src = reinterpret_cast<const float4*>(
                wdup + ((size_t)(cib * 9) * COUT + cob) * 2);
            float4* dst = reinterpret_cast<float4*>(s_w);
            const int srcRowStride = COUT / 2;   // float4s per global row
            for (int idx = tid; idx < W_ROWS * W_F4_PER_ROW; idx += NT) {
                int r  = idx / W_F4_PER_ROW;
                int c4 = idx - r * W_F4_PER_ROW;
                dst[idx] = src[(size_t)r * srcRowStride + c4];
            }
        }
        __syncthreads();

        #pragma unroll 1
        for (int ci = 0; ci < CINC; ci++) {
            // packed patch pairs: 4 rows x {(c0,c1),(c1,c2),(c2,c3)}
            float2 pr[4][3];
            #pragma unroll
            for (int r = 0; r < 4; r++) {
                const float* rowp = &s_in[ci * PH * PW + (2 * yl + r) * PW + 2 * xl];
                float2 a = *reinterpret_cast<const float2*>(rowp);
                float2 b = *reinterpret_cast<const float2*>(rowp + 2);
                pr[r][0] = a;
                pr[r][1] = make_float2(a.y, b.x);
                pr[r][2] = b;
            }
            #pragma unroll
            for (int k = 0; k < 9; k++) {
                const int ky = k / 3, kx = k % 3;
                const float4* wq = reinterpret_cast<const float4*>(
                    &s_w[((ci * 9 + k) * COCTA + cog * COPT) * 2]);
                #pragma unroll
                for (int jj = 0; jj < COPT / 2; jj++) {
                    const float4 w4 = wq[jj];
                    const float2 wlo = make_float2(w4.x, w4.y);
                    const float2 whi = make_float2(w4.z, w4.w);
                    accT[2*jj]   = fma2(pr[ky    ][kx], wlo, accT[2*jj]);
                    accB[2*jj]   = fma2(pr[ky + 1][kx], wlo, accB[2*jj]);
                    accT[2*jj+1] = fma2(pr[ky    ][kx], whi, accT[2*jj+1]);
                    accB[2*jj+1] = fma2(pr[ky + 1][kx], whi, accB[2*jj+1]);
                }
            }
        }
    }

    // relu(max(conv)+b) == max(relu(conv+b)) since relu is monotone
    const int gyp = tileY * TY + yl;
    const int gxp = tileX * TX + xl;
    if (act && gyp < HPO && gxp < WPO) {
        #pragma unroll
        for (int j = 0; j < COPT; j++) {
            const int co = cob + cog * COPT + j;
            float m = fmaxf(fmaxf(accT[j].x, accT[j].y), fmaxf(accB[j].x, accB[j].y));
            float v = fmaxf(m + bias[co], 0.f);
            out[((size_t)n * COUT + co) * (HPO * WPO) + gyp * WPO + gxp] = v;
        }
    }
}

// ---------------- prototypes: GAP of class-averaged supports, L2-normalized ----
__global__ void proto_kernel(const float* __restrict__ ytr)
{
    const int bk = blockIdx.x;
    const int b = bk / 5, k = bk - b * 5;
    const int c = threadIdx.x;

    float ssum = 0.f, ysum = 0.f;
    for (int n = 0; n < 25; n++) {
        const float y = ytr[(b * 25 + n) * 5 + k];
        ysum += y;
        if (y != 0.f) {
            const float* fp = &g_f4[((size_t)(b * 25 + n) * 512 + c) * 25];
            float sp = 0.f;
            #pragma unroll
            for (int p = 0; p < 25; p++) sp += fp[p];
            ssum = fmaf(y, sp, ssum);
        }
    }
    const float val = ssum / (ysum * 25.f);

    __shared__ float red[512];
    red[c] = val * val;
    __syncthreads();
    for (int o = 256; o > 0; o >>= 1) {
        if (c < o) red[c] += red[c + o];
        __syncthreads();
    }
    const float nrm = fmaxf(sqrtf(red[0]), 1e-12f);
    g_fa[(size_t)bk * 512 + c] = val / nrm;
}

// ---------------- classifier head: predict = l2norm(GAP(fte)) @ wc^T + bc ------
__global__ void predict_kernel(const float* __restrict__ wc, const float* __restrict__ bc,
                               float* __restrict__ out)
{
    const int q = blockIdx.x;
    const int c = threadIdx.x;

    const float* fp = &g_f4[((size_t)(100 + q) * 512 + c) * 25];
    float s = 0.f;
    #pragma unroll
    for (int p = 0; p < 25; p++) s += fp[p];
    s /= 25.f;

    __shared__ float red[512];
    __shared__ float sf[512];
    red[c] = s * s;
    __syncthreads();
    for (int o = 256; o > 0; o >>= 1) {
        if (c < o) red[c] += red[c + o];
        __syncthreads();
    }
    const float nrm = fmaxf(sqrtf(red[0]), 1e-12f);
    sf[c] = s / nrm;
    __syncthreads();

    if (c < 64) {
        float a = bc[c];
        const float* wr = &wc[(size_t)c * 512];
        #pragma unroll 8
        for (int d = 0; d < 512; d++) a = fmaf(sf[d], wr[d], a);
        out[(size_t)q * 64 + c] = a;
    }
}

// ---------------- cosine scores: (300, 5 protos, 25 positions) ------------------
__global__ void score_kernel(float* __restrict__ out)
{
    constexpr int CH = 128;
    __shared__ float sf [CH * 25];
    __shared__ float sfa[5 * 129];
    __shared__ float snrm[25];

    const int q = blockIdx.x;
    const int b = q / 75;
    const int tid = threadIdx.x;
    const float* fbase = &g_f4[(size_t)(100 + q) * 512 * 25];

    float acc = 0.f;
    const int di = tid / 25, dp = tid % 25;
    const int pn = tid - 125;

    for (int cb = 0; cb < 4; cb++) {
        __syncthreads();
        for (int idx = tid; idx < CH * 25; idx += 256)
            sf[idx] = fbase[cb * CH * 25 + idx];
        for (int idx = tid; idx < 5 * CH; idx += 256) {
            int ii = idx / CH, cc = idx - ii * CH;
            sfa[ii * 129 + cc] = g_fa[((size_t)(b * 5 + ii)) * 512 + cb * CH + cc];
        }
        __syncthreads();
        if (tid < 125) {
            #pragma unroll 4
            for (int c = 0; c < CH; c++)
                acc = fmaf(sf[c * 25 + dp], sfa[di * 129 + c], acc);
        } else if (tid < 150) {
            #pragma unroll 4
            for (int c = 0; c < CH; c++) {
                const float v = sf[c * 25 + pn];
                acc = fmaf(v, v, acc);
            }
        }
    }
    if (tid >= 125 && tid < 150) snrm[pn] = fmaxf(sqrtf(acc), 1e-12f);
    __syncthreads();
    if (tid < 125) out[(size_t)q * 125 + tid] = acc / snrm[dp];
}

// ---------------- launch ----------------
extern "C" void kernel_launch(void* const* d_in, const int* in_sizes, int n_in,
                              void* d_out, int out_size)
{
    const float* xtr = (const float*)d_in[0];
    const float* xte = (const float*)d_in[1];
    const float* ytr = (const float*)d_in[2];
    const float* w1 = (const float*)d_in[4];  const float* b1 = (const float*)d_in[5];
    const float* w2 = (const float*)d_in[6];  const float* b2 = (const float*)d_in[7];
    const float* w3 = (const float*)d_in[8];  const float* b3 = (const float*)d_in[9];
    const float* w4 = (const float*)d_in[10]; const float* b4 = (const float*)d_in[11];
    const float* wc = (const float*)d_in[12]; const float* bc = (const float*)d_in[13];
    float* out = (float*)d_out;

    float *f1, *f2, *f3, *f4, *w1d, *w2d, *w3d, *w4d;
    cudaGetSymbolAddress((void**)&f1, g_f1);
    cudaGetSymbolAddress((void**)&f2, g_f2);
    cudaGetSymbolAddress((void**)&f3, g_f3);
    cudaGetSymbolAddress((void**)&f4, g_f4);
    cudaGetSymbolAddress((void**)&w1d, g_w1d);
    cudaGetSymbolAddress((void**)&w2d, g_w2d);
    cudaGetSymbolAddress((void**)&w3d, g_w3d);
    cudaGetSymbolAddress((void**)&w4d, g_w4d);

    // weight repack (tiny)
    repack_kernel<<<8,   256>>>(w1, w1d, 3, 64);
    repack_kernel<<<144, 256>>>(w2, w2d, 64, 64);
    repack_kernel<<<288, 256>>>(w3, w3d, 64, 128);
    repack_kernel<<<2304,256>>>(w4, w4d, 128, 512);

    // L1: 3 -> 64, pooled 42x42 exact tiling 6x7 tiles of 7x6
    {
        auto kfn = conv_pool_kernel<3, 3, 64, 64, 8, 84, 84, 42, 42, 7, 6, 42>;
        const int shmem = (3*16*14 + 3*9*64*2) * 4;
        cudaFuncSetAttribute(kfn, cudaFuncAttributeMaxDynamicSharedMemorySize, shmem);
        kfn<<<dim3(42, 1, (unsigned)N_IMG), 336, shmem>>>(xtr, xte, N_SUP, w1d, b1, f1);
    }
    // L2: 64 -> 64, pooled 21x21 exact tiling 3x3 tiles of 7x7
    {
        auto kfn = conv_pool_kernel<64, 16, 64, 64, 8, 42, 42, 21, 21, 7, 7, 49>;
        const int shmem = (16*16*16 + 16*9*64*2) * 4;
        cudaFuncSetAttribute(kfn, cudaFuncAttributeMaxDynamicSharedMemorySize, shmem);
        kfn<<<dim3(9, 1, (unsigned)N_IMG), 392, shmem>>>(f1, f1, N_IMG, w2d, b2, f2);
    }
    // L3: 64 -> 128, pooled 10x10, tiles 2x2 of 5x5 (SPAD 32, 25 active)
    {
        auto kfn = conv_pool_kernel<64, 16, 128, 64, 8, 21, 21, 10, 10, 5, 5, 32>;
        const int shmem = (16*12*12 + 16*9*64*2) * 4;
        cudaFuncSetAttribute(kfn, cudaFuncAttributeMaxDynamicSharedMemorySize, shmem);
        kfn<<<dim3(4, 2, (unsigned)N_IMG), 256, shmem>>>(f2, f2, N_IMG, w3d, b3, f3);
    }
    // L4: 128 -> 512, pooled 5x5, 1 spatial tile (SPAD 32, 25 active), co tiles 8
    {
        auto kfn = conv_pool_kernel<128, 16, 512, 64, 8, 10, 10, 5, 5, 5, 5, 32>;
        const int shmem = (16*12*12 + 16*9*64*2) * 4;
        cudaFuncSetAttribute(kfn, cudaFuncAttributeMaxDynamicSharedMemorySize, shmem);
        kfn<<<dim3(1, 8, (unsigned)N_IMG), 256, shmem>>>(f3, f3, N_IMG, w4d, b4, f4);
    }

    proto_kernel<<<20, 512>>>(ytr);
    predict_kernel<<<300, 512>>>(wc, bc, out);
    score_kernel<<<300, 256>>>(out + 300 * 64);
}

// round 5
// speedup vs baseline: 2.5317x; 2.5317x over previous
#include <cuda_runtime.h>
#include <cuda_bf16.h>
#include <cstdint>
#include <math.h>

typedef __nv_bfloat16 bf16;
#define ALG __align__(128)

// ---------- scratch ----------
__device__ ALG bf16 g_a1h[400u*42*42*64];
__device__ ALG bf16 g_a1l[400u*42*42*64];
__device__ ALG bf16 g_a2h[400u*21*21*64];
__device__ ALG bf16 g_a2l[400u*21*21*64];
__device__ ALG bf16 g_a3h[400u*10*10*128];
__device__ ALG bf16 g_a3l[400u*10*10*128];
__device__ ALG float g_f4[400u*512*25];
__device__ float g_fa[4u*5*512];
__device__ ALG float g_w1d[3*9*64*2];
__device__ ALG bf16 g_w2h[9*64*64];   __device__ ALG bf16 g_w2l[9*64*64];
__device__ ALG bf16 g_w3h[9*128*64];  __device__ ALG bf16 g_w3l[9*128*64];
__device__ ALG bf16 g_w4h[9*2*512*64];__device__ ALG bf16 g_w4l[9*2*512*64];

// ---------- helpers ----------
__device__ __forceinline__ uint32_t smem_u32(const void* p) {
    uint32_t a;
    asm("{ .reg .u64 t; cvta.to.shared.u64 t, %1; cvt.u32.u64 %0, t; }" : "=r"(a) : "l"(p));
    return a;
}
__device__ __forceinline__ void ldsm_x4(uint32_t* r, uint32_t a) {
    asm volatile("ldmatrix.sync.aligned.m8n8.x4.shared.b16 {%0,%1,%2,%3}, [%4];"
        : "=r"(r[0]), "=r"(r[1]), "=r"(r[2]), "=r"(r[3]) : "r"(a));
}
__device__ __forceinline__ void ldsm_x2(uint32_t* r, uint32_t a) {
    asm volatile("ldmatrix.sync.aligned.m8n8.x2.shared.b16 {%0,%1}, [%2];"
        : "=r"(r[0]), "=r"(r[1]) : "r"(a));
}
__device__ __forceinline__ void mma16816(float4& d, const uint32_t* a, const uint32_t* b) {
    asm volatile("mma.sync.aligned.m16n8k16.row.col.f32.bf16.bf16.f32 "
        "{%0,%1,%2,%3},{%4,%5,%6,%7},{%8,%9},{%0,%1,%2,%3};"
        : "+f"(d.x), "+f"(d.y), "+f"(d.z), "+f"(d.w)
        : "r"(a[0]), "r"(a[1]), "r"(a[2]), "r"(a[3]), "r"(b[0]), "r"(b[1]));
}

// ---------- weight repacks ----------
__global__ void repack_kernel(const float* __restrict__ w, float* __restrict__ o, int cin, int cout) {
    int total = cin * 9 * cout;
    for (int i = blockIdx.x*blockDim.x + threadIdx.x; i < total; i += gridDim.x*blockDim.x) {
        int co = i % cout, rem = i / cout;
        float v = w[(size_t)co*cin*9 + rem];
        o[2*(size_t)i] = v; o[2*(size_t)i+1] = v;
    }
}
// [cout][cin][9] fp32 -> [k][cic][co][64ci] bf16 hi/lo
__global__ void repack_bf16_kernel(const float* __restrict__ w, bf16* __restrict__ oh,
                                   bf16* __restrict__ ol, int cin, int cout) {
    int nc = cin / 64, total = 9 * nc * cout * 64;
    for (int i = blockIdx.x*blockDim.x + threadIdx.x; i < total; i += gridDim.x*blockDim.x) {
        int cil = i & 63, t = i >> 6;
        int co = t % cout; t /= cout;
        int cic = t % nc;  t /= nc;
        int k = t;
        float v = w[((size_t)co*cin + cic*64 + cil)*9 + k];
        bf16 h = __float2bfloat16(v);
        oh[i] = h; ol[i] = __float2bfloat16(v - __bfloat162float(h));
    }
}

// ---------- L1: scalar conv+pool -> NHWC bf16 hi/lo ----------
typedef unsigned long long u64_t;
__device__ __forceinline__ float2 fma2(float2 a, float2 b, float2 c) {
    float2 d;
    asm("fma.rn.f32x2 %0, %1, %2, %3;" : "=l"(*reinterpret_cast<u64_t*>(&d))
        : "l"(*reinterpret_cast<const u64_t*>(&a)), "l"(*reinterpret_cast<const u64_t*>(&b)),
          "l"(*reinterpret_cast<const u64_t*>(&c)));
    return d;
}
__global__ void __launch_bounds__(336)
conv1_kernel(const float* __restrict__ inA, const float* __restrict__ inB, int nsplit,
             const float* __restrict__ wdup, const float* __restrict__ bias,
             bf16* __restrict__ outh, bf16* __restrict__ outl)
{
    constexpr int PH = 16, PW = 14, NT = 336;
    __shared__ __align__(16) float s_in[3*PH*PW];
    __shared__ __align__(16) float s_w[3*9*128];
    const int n = blockIdx.z;
    const int tileY = blockIdx.x / 7, tileX = blockIdx.x % 7;
    const int tid = threadIdx.x, s = tid % 42, cog = tid / 42;
    const int yl = s / 6, xl = s % 6;
    const int oy = 2*(tileY*7) - 1, ox = 2*(tileX*6) - 1;
    const float* img = (n < nsplit) ? inA + (size_t)n*3*84*84 : inB + (size_t)(n-nsplit)*3*84*84;

    float2 accT[8], accB[8];
    #pragma unroll
    for (int j = 0; j < 8; j++) { accT[j] = make_float2(0,0); accB[j] = make_float2(0,0); }

    for (int idx = tid; idx < 3*PH*PW; idx += NT) {
        int ci = idx/(PH*PW), rem = idx - ci*(PH*PW), r = rem/PW, cl = rem - r*PW;
        int gy = oy + r, gx = ox + cl;
        float v = 0.f;
        if (gy >= 0 && gy < 84 && gx >= 0 && gx < 84) v = img[((size_t)ci*84 + gy)*84 + gx];
        s_in[idx] = v;
    }
    for (int idx = tid; idx < 3*9*32; idx += NT)
        reinterpret_cast<float4*>(s_w)[idx] = reinterpret_cast<const float4*>(wdup)[idx];
    __syncthreads();

    #pragma unroll
    for (int ci = 0; ci < 3; ci++) {
        float2 pr[4][3];
        #pragma unroll
        for (int r = 0; r < 4; r++) {
            const float* rp = &s_in[ci*PH*PW + (2*yl + r)*PW + 2*xl];
            float2 a = *reinterpret_cast<const float2*>(rp);
            float2 b = *reinterpret_cast<const float2*>(rp + 2);
            pr[r][0] = a; pr[r][1] = make_float2(a.y, b.x); pr[r][2] = b;
        }
        #pragma unroll
        for (int k = 0; k < 9; k++) {
            int ky = k/3, kx = k%3;
            const float4* wq = reinterpret_cast<const float4*>(&s_w[(ci*9 + k)*128 + cog*16]);
            #pragma unroll
            for (int jj = 0; jj < 4; jj++) {
                float4 w4 = wq[jj];
                float2 wlo = make_float2(w4.x, w4.y), whi = make_float2(w4.z, w4.w);
                accT[2*jj]   = fma2(pr[ky][kx],   wlo, accT[2*jj]);
                accB[2*jj]   = fma2(pr[ky+1][kx], wlo, accB[2*jj]);
                accT[2*jj+1] = fma2(pr[ky][kx],   whi, accT[2*jj+1]);
                accB[2*jj+1] = fma2(pr[ky+1][kx], whi, accB[2*jj+1]);
            }
        }
    }
    const int gyp = tileY*7 + yl, gxp = tileX*6 + xl;
    unsigned short hb[8], lb[8];
    #pragma unroll
    for (int j = 0; j < 8; j++) {
        float m = fmaxf(fmaxf(accT[j].x, accT[j].y), fmaxf(accB[j].x, accB[j].y));
        float v = fmaxf(m + bias[cog*8 + j], 0.f);
        bf16 h = __float2bfloat16(v);
        bf16 l = __float2bfloat16(v - __bfloat162float(h));
        hb[j] = __bfloat16_as_ushort(h); lb[j] = __bfloat16_as_ushort(l);
    }
    size_t base = (((size_t)n*42 + gyp)*42 + gxp)*64 + cog*8;
    *reinterpret_cast<uint4*>(outh + base) =
        make_uint4(hb[0]|((uint32_t)hb[1]<<16), hb[2]|((uint32_t)hb[3]<<16),
                   hb[4]|((uint32_t)hb[5]<<16), hb[6]|((uint32_t)hb[7]<<16));
    *reinterpret_cast<uint4*>(outl + base) =
        make_uint4(lb[0]|((uint32_t)lb[1]<<16), lb[2]|((uint32_t)lb[3]<<16),
                   lb[4]|((uint32_t)lb[5]<<16), lb[6]|((uint32_t)lb[7]<<16));
}

// ---------- HMMA conv, pixels-on-M (L2, L3): CIN=64 ----------
// M tile = 128 conv pixels (m = 4*pooled + quadrant), N = COUT, K = 9 taps x 64ci.
template<int COUT, int HIN, int WIN, int HPO, int WPO>
__global__ void __launch_bounds__(256)
conv_mma_px(const bf16* __restrict__ inh, const bf16* __restrict__ inl,
            const bf16* __restrict__ wh,  const bf16* __restrict__ wl,
            const float* __restrict__ bias,
            bf16* __restrict__ outh, bf16* __restrict__ outl)
{
    constexpr int NB = COUT/8;
    constexpr int CB = COUT*128;
    constexpr uint32_t oAh = 1024, oAl = 1024 + 16384, oBh = 33792, oBl = 33792 + CB;

    extern __shared__ char dsm[];
    char* smp = (char*)(((uintptr_t)dsm + 1023) & ~(uintptr_t)1023);
    const uint32_t sb = smem_u32(smp);
    const int tid = threadIdx.x, wid = tid >> 5, lane = tid & 31;
    const int img = blockIdx.z, ppb = blockIdx.x * 32;

    const bf16* ih = inh + (size_t)img * HIN * WIN * 64;
    const bf16* il = inl + (size_t)img * HIN * WIN * 64;

    float4 acc[NB];
    #pragma unroll
    for (int i = 0; i < NB; i++) acc[i] = make_float4(0,0,0,0);

    const int aRow = wid*16 + (lane & 15);
    const uint32_t aHiB = sb + oAh + aRow*128, aLoB = sb + oAl + aRow*128;
    const int aXor = aRow & 7, aHalf = lane >> 4;
    const int bRow = lane & 7, bHalf = (lane >> 3) & 1;

    for (int k = 0; k < 9; k++) {
        const int ky = k/3 - 1, kx = k%3 - 1;
        __syncthreads();
        // stage A (128 px rows x 128B) hi/lo
        for (int g = tid; g < 1024; g += 256) {
            int m = g >> 3, seg = g & 7;
            int pp = ppb + (m >> 2), q = m & 3;
            uint4 vh = make_uint4(0,0,0,0), vl = vh;
            if (pp < HPO*WPO) {
                int y = 2*(pp/WPO) + (q>>1) + ky;
                int x = 2*(pp%WPO) + (q&1) + kx;
                if (y >= 0 && y < HIN && x >= 0 && x < WIN) {
                    size_t s = ((size_t)y*WIN + x)*64 + seg*8;
                    vh = *reinterpret_cast<const uint4*>(ih + s);
                    vl = *reinterpret_cast<const uint4*>(il + s);
                }
            }
            uint32_t d = m*128 + ((seg ^ (m & 7)) << 4);
            *reinterpret_cast<uint4*>(smp + oAh + d) = vh;
            *reinterpret_cast<uint4*>(smp + oAl + d) = vl;
        }
        // stage B (COUT co rows x 128B) hi/lo
        for (int g = tid; g < COUT*8; g += 256) {
            int r = g >> 3, seg = g & 7;
            size_t s = ((size_t)k*COUT + r)*64 + seg*8;
            uint32_t d = r*128 + ((seg ^ (r & 7)) << 4);
            *reinterpret_cast<uint4*>(smp + oBh + d) = *reinterpret_cast<const uint4*>(wh + s);
            *reinterpret_cast<uint4*>(smp + oBl + d) = *reinterpret_cast<const uint4*>(wl + s);
        }
        __syncthreads();
        #pragma unroll
        for (int ks = 0; ks < 4; ks++) {
            uint32_t ah[4], al[4];
            const uint32_t ao = (uint32_t)(((2*ks + aHalf) ^ aXor) << 4);
            ldsm_x4(ah, aHiB + ao);
            ldsm_x4(al, aLoB + ao);
            #pragma unroll
            for (int nb = 0; nb < NB; nb++) {
                const uint32_t bo = (uint32_t)((nb*8 + bRow)*128 + (((2*ks + bHalf) ^ bRow) << 4));
                uint32_t bh[2], bl[2];
                ldsm_x2(bh, sb + oBh + bo);
                ldsm_x2(bl, sb + oBl + bo);
                mma16816(acc[nb], ah, bh);
                mma16816(acc[nb], al, bh);
                mma16816(acc[nb], ah, bl);
            }
        }
    }

    // epilogue: dump -> pool -> bias/relu -> NHWC hi/lo
    __syncthreads();
    float* so = reinterpret_cast<float*>(smp + 1024);
    {
        const int row = wid*16 + (lane >> 2);
        const int col = 2*(lane & 3);
        #pragma unroll
        for (int nb = 0; nb < NB; nb++) {
            so[row*COUT + nb*8 + col]       = acc[nb].x;
            so[row*COUT + nb*8 + col + 1]   = acc[nb].y;
            so[(row+8)*COUT + nb*8 + col]   = acc[nb].z;
            so[(row+8)*COUT + nb*8 + col+1] = acc[nb].w;
        }
    }
    __syncthreads();
    for (int g = tid; g < 32*NB; g += 256) {
        int pp_l = g / NB, cg = g % NB;
        int pp = ppb + pp_l;
        if (pp >= HPO*WPO) continue;
        int co0 = cg*8;
        float v[8];
        #pragma unroll
        for (int j = 0; j < 8; j++) v[j] = -1e30f;
        #pragma unroll
        for (int q = 0; q < 4; q++) {
            const float* rp = &so[(4*pp_l + q)*COUT + co0];
            #pragma unroll
            for (int j = 0; j < 8; j++) v[j] = fmaxf(v[j], rp[j]);
        }
        unsigned short hh[8], ll[8];
        #pragma unroll
        for (int j = 0; j < 8; j++) {
            float t = fmaxf(v[j] + bias[co0 + j], 0.f);
            bf16 h = __float2bfloat16(t);
            hh[j] = __bfloat16_as_ushort(h);
            ll[j] = __bfloat16_as_ushort(__float2bfloat16(t - __bfloat162float(h)));
        }
        size_t base = (((size_t)img*HPO + pp/WPO)*WPO + pp%WPO)*COUT + co0;
        *reinterpret_cast<uint4*>(outh + base) =
            make_uint4(hh[0]|((uint32_t)hh[1]<<16), hh[2]|((uint32_t)hh[3]<<16),
                       hh[4]|((uint32_t)hh[5]<<16), hh[6]|((uint32_t)hh[7]<<16));
        *reinterpret_cast<uint4*>(outl + base) =
            make_uint4(ll[0]|((uint32_t)ll[1]<<16), ll[2]|((uint32_t)ll[3]<<16),
                       ll[4]|((uint32_t)ll[5]<<16), ll[6]|((uint32_t)ll[7]<<16));
    }
}

// ---------- HMMA conv, co-on-M (L4): CIN=128, COUT=512, 10x10 -> 5x5 fp32 NCHW ----------
__global__ void __launch_bounds__(256)
conv_mma_co(const bf16* __restrict__ inh, const bf16* __restrict__ inl,
            const bf16* __restrict__ wh,  const bf16* __restrict__ wl,
            const float* __restrict__ bias, float* __restrict__ outf)
{
    constexpr int NB = 13;               // N = 104 pixels (4 pad rows)
    constexpr uint32_t oAh = 1024, oAl = 17408, oBh = 33792, oBl = 47104;

    extern __shared__ char dsm[];
    char* smp = (char*)(((uintptr_t)dsm + 1023) & ~(uintptr_t)1023);
    const uint32_t sb = smem_u32(smp);
    const int tid = threadIdx.x, wid = tid >> 5, lane = tid & 31;
    const int img = blockIdx.z, cob = blockIdx.y * 128;

    const bf16* ih = inh + (size_t)img * 100 * 128;
    const bf16* il = inl + (size_t)img * 100 * 128;

    float4 acc[NB];
    #pragma unroll
    for (int i = 0; i < NB; i++) acc[i] = make_float4(0,0,0,0);

    const int aRow = wid*16 + (lane & 15);
    const uint32_t aHiB = sb + oAh + aRow*128, aLoB = sb + oAl + aRow*128;
    const int aXor = aRow & 7, aHalf = lane >> 4;
    const int bRow = lane & 7, bHalf = (lane >> 3) & 1;

    for (int it = 0; it < 18; it++) {
        const int k = it >> 1, cic = it & 1;
        const int dy = k/3 - 1, dx = k%3 - 1;
        __syncthreads();
        // A: weights [128 co][64ci]
        for (int g = tid; g < 1024; g += 256) {
            int m = g >> 3, seg = g & 7;
            size_t s = ((size_t)(k*2 + cic)*512 + cob + m)*64 + seg*8;
            uint32_t d = m*128 + ((seg ^ (m & 7)) << 4);
            *reinterpret_cast<uint4*>(smp + oAh + d) = *reinterpret_cast<const uint4*>(wh + s);
            *reinterpret_cast<uint4*>(smp + oAl + d) = *reinterpret_cast<const uint4*>(wl + s);
        }
        // B: shifted pixels [104][64ci]
        for (int g = tid; g < 104*8; g += 256) {
            int m = g >> 3, seg = g & 7;
            int pp = m >> 2, q = m & 3;
            uint4 vh = make_uint4(0,0,0,0), vl = vh;
            if (pp < 25) {
                int y = 2*(pp/5) + (q>>1) + dy;
                int x = 2*(pp%5) + (q&1) + dx;
                if (y >= 0 && y < 10 && x >= 0 && x < 10) {
                    size_t s = ((size_t)y*10 + x)*128 + cic*64 + seg*8;
                    vh = *reinterpret_cast<const uint4*>(ih + s);
                    vl = *reinterpret_cast<const uint4*>(il + s);
                }
            }
            uint32_t d = m*128 + ((seg ^ (m & 7)) << 4);
            *reinterpret_cast<uint4*>(smp + oBh + d) = vh;
            *reinterpret_cast<uint4*>(smp + oBl + d) = vl;
        }
        __syncthreads();
        #pragma unroll
        for (int ks = 0; ks < 4; ks++) {
            uint32_t ah[4], al[4];
            const uint32_t ao = (uint32_t)(((2*ks + aHalf) ^ aXor) << 4);
            ldsm_x4(ah, aHiB + ao);
            ldsm_x4(al, aLoB + ao);
            #pragma unroll
            for (int nb = 0; nb < NB; nb++) {
                const uint32_t bo = (uint32_t)((nb*8 + bRow)*128 + (((2*ks + bHalf) ^ bRow) << 4));
                uint32_t bh[2], bl[2];
                ldsm_x2(bh, sb + oBh + bo);
                ldsm_x2(bl, sb + oBl + bo);
                mma16816(acc[nb], ah, bh);
                mma16816(acc[nb], al, bh);
                mma16816(acc[nb], ah, bl);
            }
        }
    }

    __syncthreads();
    float* so = reinterpret_cast<float*>(smp + 1024);   // [128 co][104 px]
    {
        const int row = wid*16 + (lane >> 2);
        const int col = 2*(lane & 3);
        #pragma unroll
        for (int nb = 0; nb < NB; nb++) {
            so[row*104 + nb*8 + col]       = acc[nb].x;
            so[row*104 + nb*8 + col + 1]   = acc[nb].y;
            so[(row+8)*104 + nb*8 + col]   = acc[nb].z;
            so[(row+8)*104 + nb*8 + col+1] = acc[nb].w;
        }
    }
    __syncthreads();
    for (int g = tid; g < 3200; g += 256) {
        int co_l = g / 25, pp = g % 25;
        float4 q4 = *reinterpret_cast<float4*>(&so[co_l*104 + 4*pp]);
        float v = fmaxf(fmaxf(q4.x, q4.y), fmaxf(q4.z, q4.w));
        v = fmaxf(v + bias[cob + co_l], 0.f);
        outf[((size_t)img*512 + cob + co_l)*25 + pp] = v;
    }
}

// ---------- prototypes / head / scores ----------
__global__ void proto_kernel(const float* __restrict__ ytr) {
    const int bk = blockIdx.x, b = bk/5, k = bk - b*5, c = threadIdx.x;
    float ssum = 0.f, ysum = 0.f;
    for (int n = 0; n < 25; n++) {
        float y = ytr[(b*25 + n)*5 + k];
        ysum += y;
        if (y != 0.f) {
            const float* fp = &g_f4[((size_t)(b*25 + n)*512 + c)*25];
            float sp = 0.f;
            #pragma unroll
            for (int p = 0; p < 25; p++) sp += fp[p];
            ssum = fmaf(y, sp, ssum);
        }
    }
    float val = ssum / (ysum * 25.f);
    __shared__ float red[512];
    red[c] = val*val; __syncthreads();
    for (int o = 256; o > 0; o >>= 1) { if (c < o) red[c] += red[c+o]; __syncthreads(); }
    g_fa[(size_t)bk*512 + c] = val / fmaxf(sqrtf(red[0]), 1e-12f);
}
__global__ void predict_kernel(const float* __restrict__ wc, const float* __restrict__ bc,
                               float* __restrict__ out) {
    const int q = blockIdx.x, c = threadIdx.x;
    const float* fp = &g_f4[((size_t)(100 + q)*512 + c)*25];
    float s = 0.f;
    #pragma unroll
    for (int p = 0; p < 25; p++) s += fp[p];
    s /= 25.f;
    __shared__ float red[512], sf[512];
    red[c] = s*s; __syncthreads();
    for (int o = 256; o > 0; o >>= 1) { if (c < o) red[c] += red[c+o]; __syncthreads(); }
    sf[c] = s / fmaxf(sqrtf(red[0]), 1e-12f);
    __syncthreads();
    if (c < 64) {
        float a = bc[c];
        const float* wr = &wc[(size_t)c*512];
        #pragma unroll 8
        for (int d = 0; d < 512; d++) a = fmaf(sf[d], wr[d], a);
        out[(size_t)q*64 + c] = a;
    }
}
__global__ void score_kernel(float* __restrict__ out) {
    constexpr int CH = 128;
    __shared__ float sf[CH*25], sfa[5*129], snrm[25];
    const int q = blockIdx.x, b = q/75, tid = threadIdx.x;
    const float* fbase = &g_f4[(size_t)(100 + q)*512*25];
    float acc = 0.f;
    const int di = tid/25, dp = tid%25, pn = tid - 125;
    for (int cb = 0; cb < 4; cb++) {
        __syncthreads();
        for (int i = tid; i < CH*25; i += 256) sf[i] = fbase[cb*CH*25 + i];
        for (int i = tid; i < 5*CH; i += 256) {
            int ii = i/CH, cc = i - ii*CH;
            sfa[ii*129 + cc] = g_fa[((size_t)(b*5 + ii))*512 + cb*CH + cc];
        }
        __syncthreads();
        if (tid < 125) {
            #pragma unroll 4
            for (int c = 0; c < CH; c++) acc = fmaf(sf[c*25 + dp], sfa[di*129 + c], acc);
        } else if (tid < 150) {
            #pragma unroll 4
            for (int c = 0; c < CH; c++) { float v = sf[c*25 + pn]; acc = fmaf(v, v, acc); }
        }
    }
    if (tid >= 125 && tid < 150) snrm[pn] = fmaxf(sqrtf(acc), 1e-12f);
    __syncthreads();
    if (tid < 125) out[(size_t)q*125 + tid] = acc / snrm[dp];
}

// ---------- launch ----------
extern "C" void kernel_launch(void* const* d_in, const int* in_sizes, int n_in,
                              void* d_out, int out_size)
{
    const float* xtr = (const float*)d_in[0];
    const float* xte = (const float*)d_in[1];
    const float* ytr = (const float*)d_in[2];
    const float* w1 = (const float*)d_in[4];  const float* b1 = (const float*)d_in[5];
    const float* w2 = (const float*)d_in[6];  const float* b2 = (const float*)d_in[7];
    const float* w3 = (const float*)d_in[8];  const float* b3 = (const float*)d_in[9];
    const float* w4 = (const float*)d_in[10]; const float* b4 = (const float*)d_in[11];
    const float* wc = (const float*)d_in[12]; const float* bc = (const float*)d_in[13];
    float* out = (float*)d_out;

    float *f4, *w1d;
    bf16 *a1h,*a1l,*a2h,*a2l,*a3h,*a3l,*w2h,*w2l,*w3h,*w3l,*w4h,*w4l;
    cudaGetSymbolAddress((void**)&f4, g_f4);
    cudaGetSymbolAddress((void**)&w1d, g_w1d);
    cudaGetSymbolAddress((void**)&a1h, g_a1h); cudaGetSymbolAddress((void**)&a1l, g_a1l);
    cudaGetSymbolAddress((void**)&a2h, g_a2h); cudaGetSymbolAddress((void**)&a2l, g_a2l);
    cudaGetSymbolAddress((void**)&a3h, g_a3h); cudaGetSymbolAddress((void**)&a3l, g_a3l);
    cudaGetSymbolAddress((void**)&w2h, g_w2h); cudaGetSymbolAddress((void**)&w2l, g_w2l);
    cudaGetSymbolAddress((void**)&w3h, g_w3h); cudaGetSymbolAddress((void**)&w3l, g_w3l);
    cudaGetSymbolAddress((void**)&w4h, g_w4h); cudaGetSymbolAddress((void**)&w4l, g_w4l);

    repack_kernel<<<8, 256>>>(w1, w1d, 3, 64);
    repack_bf16_kernel<<<144, 256>>>(w2, w2h, w2l, 64, 64);
    repack_bf16_kernel<<<288, 256>>>(w3, w3h, w3l, 64, 128);
    repack_bf16_kernel<<<2304, 256>>>(w4, w4h, w4l, 128, 512);

    conv1_kernel<<<dim3(42, 1, 400), 336>>>(xtr, xte, 100, w1d, b1, a1h, a1l);

    {   // L2: 64->64, pooled 21x21=441 -> 14 tiles of 32
        auto kfn = conv_mma_px<64, 42, 42, 21, 21>;
        int sm = 51200;
        cudaFuncSetAttribute(kfn, cudaFuncAttributeMaxDynamicSharedMemorySize, sm);
        kfn<<<dim3(14, 1, 400), 256, sm>>>(a1h, a1l, w2h, w2l, b2, a2h, a2l);
    }
    {   // L3: 64->128, pooled 10x10=100 -> 4 tiles
        auto kfn = conv_mma_px<128, 21, 21, 10, 10>;
        int sm = 67584;
        cudaFuncSetAttribute(kfn, cudaFuncAttributeMaxDynamicSharedMemorySize, sm);
        kfn<<<dim3(4, 1, 400), 256, sm>>>(a2h, a2l, w3h, w3l, b3, a3h, a3l);
    }
    {   // L4: 128->512, 4 co tiles of 128
        int sm = 61440;
        cudaFuncSetAttribute(conv_mma_co, cudaFuncAttributeMaxDynamicSharedMemorySize, sm);
        conv_mma_co<<<dim3(1, 4, 400), 256, sm>>>(a3h, a3l, w4h, w4l, b4, f4);
    }

    proto_kernel<<<20, 512>>>(ytr);
    predict_kernel<<<300, 512>>>(wc, bc, out);
    score_kernel<<<300, 256>>>(out + 300*64);
}

// round 6
// speedup vs baseline: 2.8493x; 1.1254x over previous
#include <cuda_runtime.h>
#include <cuda_bf16.h>
#include <cstdint>
#include <math.h>

typedef __nv_bfloat16 bf16;
#define ALG __align__(128)

// ---------- scratch ----------
__device__ ALG bf16 g_a1h[400u*42*42*64];
__device__ ALG bf16 g_a1l[400u*42*42*64];
__device__ ALG bf16 g_a2h[400u*21*21*64];
__device__ ALG bf16 g_a2l[400u*21*21*64];
__device__ ALG bf16 g_a3h[400u*10*10*128];
__device__ ALG bf16 g_a3l[400u*10*10*128];
__device__ ALG float g_f4[400u*512*25];
__device__ float g_fa[4u*5*512];
__device__ ALG float g_w1d[3*9*64*2];
__device__ ALG bf16 g_w2h[9*64*64];   __device__ ALG bf16 g_w2l[9*64*64];
__device__ ALG bf16 g_w3h[9*128*64];  __device__ ALG bf16 g_w3l[9*128*64];
__device__ ALG bf16 g_w4h[9*2*512*64];__device__ ALG bf16 g_w4l[9*2*512*64];

// ---------- helpers ----------
__device__ __forceinline__ uint32_t smem_u32(const void* p) {
    uint32_t a;
    asm("{ .reg .u64 t; cvta.to.shared.u64 t, %1; cvt.u32.u64 %0, t; }" : "=r"(a) : "l"(p));
    return a;
}
__device__ __forceinline__ void ldsm_x4(uint32_t* r, uint32_t a) {
    asm volatile("ldmatrix.sync.aligned.m8n8.x4.shared.b16 {%0,%1,%2,%3}, [%4];"
        : "=r"(r[0]), "=r"(r[1]), "=r"(r[2]), "=r"(r[3]) : "r"(a));
}
__device__ __forceinline__ void ldsm_x2(uint32_t* r, uint32_t a) {
    asm volatile("ldmatrix.sync.aligned.m8n8.x2.shared.b16 {%0,%1}, [%2];"
        : "=r"(r[0]), "=r"(r[1]) : "r"(a));
}
__device__ __forceinline__ void mma16816(float4& d, const uint32_t* a, const uint32_t* b) {
    asm volatile("mma.sync.aligned.m16n8k16.row.col.f32.bf16.bf16.f32 "
        "{%0,%1,%2,%3},{%4,%5,%6,%7},{%8,%9},{%0,%1,%2,%3};"
        : "+f"(d.x), "+f"(d.y), "+f"(d.z), "+f"(d.w)
        : "r"(a[0]), "r"(a[1]), "r"(a[2]), "r"(a[3]), "r"(b[0]), "r"(b[1]));
}
__device__ __forceinline__ void cpa16(uint32_t dst, const void* src, int sz) {
    asm volatile("cp.async.cg.shared.global [%0], [%1], 16, %2;"
                 :: "r"(dst), "l"(src), "r"(sz) : "memory");
}
#define CPA_COMMIT() asm volatile("cp.async.commit_group;" ::: "memory")
#define CPA_WAIT0()  asm volatile("cp.async.wait_group 0;" ::: "memory")

// ---------- weight repacks ----------
__global__ void repack_kernel(const float* __restrict__ w, float* __restrict__ o, int cin, int cout) {
    int total = cin * 9 * cout;
    for (int i = blockIdx.x*blockDim.x + threadIdx.x; i < total; i += gridDim.x*blockDim.x) {
        int co = i % cout, rem = i / cout;
        float v = w[(size_t)co*cin*9 + rem];
        o[2*(size_t)i] = v; o[2*(size_t)i+1] = v;
    }
}
__global__ void repack_bf16_kernel(const float* __restrict__ w, bf16* __restrict__ oh,
                                   bf16* __restrict__ ol, int cin, int cout) {
    int nc = cin / 64, total = 9 * nc * cout * 64;
    for (int i = blockIdx.x*blockDim.x + threadIdx.x; i < total; i += gridDim.x*blockDim.x) {
        int cil = i & 63, t = i >> 6;
        int co = t % cout; t /= cout;
        int cic = t % nc;  t /= nc;
        int k = t;
        float v = w[((size_t)co*cin + cic*64 + cil)*9 + k];
        bf16 h = __float2bfloat16(v);
        oh[i] = h; ol[i] = __float2bfloat16(v - __bfloat162float(h));
    }
}

// ---------- L1: scalar conv+pool -> NHWC bf16 hi/lo ----------
typedef unsigned long long u64_t;
__device__ __forceinline__ float2 fma2(float2 a, float2 b, float2 c) {
    float2 d;
    asm("fma.rn.f32x2 %0, %1, %2, %3;" : "=l"(*reinterpret_cast<u64_t*>(&d))
        : "l"(*reinterpret_cast<const u64_t*>(&a)), "l"(*reinterpret_cast<const u64_t*>(&b)),
          "l"(*reinterpret_cast<const u64_t*>(&c)));
    return d;
}
__global__ void __launch_bounds__(336)
conv1_kernel(const float* __restrict__ inA, const float* __restrict__ inB, int nsplit,
             const float* __restrict__ wdup, const float* __restrict__ bias,
             bf16* __restrict__ outh, bf16* __restrict__ outl)
{
    constexpr int PH = 16, PW = 14, NT = 336;
    __shared__ __align__(16) float s_in[3*PH*PW];
    __shared__ __align__(16) float s_w[3*9*128];
    const int n = blockIdx.z;
    const int tileY = blockIdx.x / 7, tileX = blockIdx.x % 7;
    const int tid = threadIdx.x, s = tid % 42, cog = tid / 42;
    const int yl = s / 6, xl = s % 6;
    const int oy = 2*(tileY*7) - 1, ox = 2*(tileX*6) - 1;
    const float* img = (n < nsplit) ? inA + (size_t)n*3*84*84 : inB + (size_t)(n-nsplit)*3*84*84;

    float2 accT[8], accB[8];
    #pragma unroll
    for (int j = 0; j < 8; j++) { accT[j] = make_float2(0,0); accB[j] = make_float2(0,0); }

    for (int idx = tid; idx < 3*PH*PW; idx += NT) {
        int ci = idx/(PH*PW), rem = idx - ci*(PH*PW), r = rem/PW, cl = rem - r*PW;
        int gy = oy + r, gx = ox + cl;
        float v = 0.f;
        if (gy >= 0 && gy < 84 && gx >= 0 && gx < 84) v = img[((size_t)ci*84 + gy)*84 + gx];
        s_in[idx] = v;
    }
    for (int idx = tid; idx < 3*9*32; idx += NT)
        reinterpret_cast<float4*>(s_w)[idx] = reinterpret_cast<const float4*>(wdup)[idx];
    __syncthreads();

    #pragma unroll
    for (int ci = 0; ci < 3; ci++) {
        float2 pr[4][3];
        #pragma unroll
        for (int r = 0; r < 4; r++) {
            const float* rp = &s_in[ci*PH*PW + (2*yl + r)*PW + 2*xl];
            float2 a = *reinterpret_cast<const float2*>(rp);
            float2 b = *reinterpret_cast<const float2*>(rp + 2);
            pr[r][0] = a; pr[r][1] = make_float2(a.y, b.x); pr[r][2] = b;
        }
        #pragma unroll
        for (int k = 0; k < 9; k++) {
            int ky = k/3, kx = k%3;
            const float4* wq = reinterpret_cast<const float4*>(&s_w[(ci*9 + k)*128 + cog*16]);
            #pragma unroll
            for (int jj = 0; jj < 4; jj++) {
                float4 w4 = wq[jj];
                float2 wlo = make_float2(w4.x, w4.y), whi = make_float2(w4.z, w4.w);
                accT[2*jj]   = fma2(pr[ky][kx],   wlo, accT[2*jj]);
                accB[2*jj]   = fma2(pr[ky+1][kx], wlo, accB[2*jj]);
                accT[2*jj+1] = fma2(pr[ky][kx],   whi, accT[2*jj+1]);
                accB[2*jj+1] = fma2(pr[ky+1][kx], whi, accB[2*jj+1]);
            }
        }
    }
    const int gyp = tileY*7 + yl, gxp = tileX*6 + xl;
    unsigned short hb[8], lb[8];
    #pragma unroll
    for (int j = 0; j < 8; j++) {
        float m = fmaxf(fmaxf(accT[j].x, accT[j].y), fmaxf(accB[j].x, accB[j].y));
        float v = fmaxf(m + bias[cog*8 + j], 0.f);
        bf16 h = __float2bfloat16(v);
        bf16 l = __float2bfloat16(v - __bfloat162float(h));
        hb[j] = __bfloat16_as_ushort(h); lb[j] = __bfloat16_as_ushort(l);
    }
    size_t base = (((size_t)n*42 + gyp)*42 + gxp)*64 + cog*8;
    *reinterpret_cast<uint4*>(outh + base) =
        make_uint4(hb[0]|((uint32_t)hb[1]<<16), hb[2]|((uint32_t)hb[3]<<16),
                   hb[4]|((uint32_t)hb[5]<<16), hb[6]|((uint32_t)hb[7]<<16));
    *reinterpret_cast<uint4*>(outl + base) =
        make_uint4(lb[0]|((uint32_t)lb[1]<<16), lb[2]|((uint32_t)lb[3]<<16),
                   lb[4]|((uint32_t)lb[5]<<16), lb[6]|((uint32_t)lb[7]<<16));
}

// ---------- HMMA conv, pixels-on-M (L2, L3): CIN=64 ----------
// Resident swizzled halo band (A); weights (B) double-buffered via cp.async.
template<int COUT, int HIN, int WIN, int HPO, int WPO, int NROWS, int PW>
__global__ void __launch_bounds__(256)
conv_mma_px(const bf16* __restrict__ inh, const bf16* __restrict__ inl,
            const bf16* __restrict__ wh,  const bf16* __restrict__ wl,
            const float* __restrict__ bias,
            bf16* __restrict__ outh, bf16* __restrict__ outl)
{
    constexpr int NB = COUT/8;
    constexpr int BANDPX = NROWS*PW;
    constexpr uint32_t BH = BANDPX*128;
    constexpr uint32_t CB = COUT*128;
    constexpr uint32_t oB = 2*BH;

    extern __shared__ char dsm[];
    char* smp = (char*)(((uintptr_t)dsm + 1023) & ~(uintptr_t)1023);
    const uint32_t sb = smem_u32(smp);
    const int tid = threadIdx.x, wid = tid >> 5, lane = tid & 31;
    const int img = blockIdx.z, ppb = blockIdx.x * 32;
    const int r0 = ppb / WPO;
    const int ystart = 2*r0 - 1;

    const bf16* ih = inh + (size_t)img * HIN * WIN * 64;
    const bf16* il = inl + (size_t)img * HIN * WIN * 64;

    // ---- stage halo band once (swizzled by pixel&7), zero-fill OOB ----
    for (int g = tid; g < BANDPX*8; g += 256) {
        int p = g >> 3, seg = g & 7;
        int row = p / PW, col = p % PW;
        int gy = ystart + row, gx = col - 1;
        bool ok = (gy >= 0 && gy < HIN && gx >= 0 && gx < WIN);
        size_t s = ok ? (((size_t)gy*WIN + gx)*64 + seg*8) : 0;
        uint32_t d = p*128 + ((seg ^ (p & 7)) << 4);
        cpa16(sb + d,      ih + s, ok ? 16 : 0);
        cpa16(sb + BH + d, il + s, ok ? 16 : 0);
    }
    CPA_COMMIT();

    // ---- prefetch B tap 0 ----
    {
        const uint32_t bb = sb + oB;
        for (int g = tid; g < COUT*8; g += 256) {
            int r = g >> 3, seg = g & 7;
            uint32_t d = bb + r*128 + ((seg ^ (r & 7)) << 4);
            size_t s = (size_t)r*64 + seg*8;
            cpa16(d,      wh + s, 16);
            cpa16(d + CB, wl + s, 16);
        }
        CPA_COMMIT();
    }

    float4 acc[NB];
    #pragma unroll
    for (int i = 0; i < NB; i++) acc[i] = make_float4(0,0,0,0);

    // per-lane A pixel base (tap (0,0) => conv offset (-1,-1))
    const int aRow = wid*16 + (lane & 15);
    const int appd = aRow >> 2, aq = aRow & 3;
    const int ay = 2*((ppb + appd)/WPO) + (aq >> 1);
    const int ax = 2*((ppb + appd)%WPO) + (aq & 1);
    const int p00 = (ay - 2*r0)*PW + ax;
    const int aHalf = lane >> 4;
    const int bRow = lane & 7, bHalf = (lane >> 3) & 1;

    for (int k = 0; k < 9; k++) {
        CPA_WAIT0();
        __syncthreads();
        if (k < 8) {   // prefetch next tap's weights into the other buffer
            const uint32_t bb = sb + oB + ((k+1) & 1)*(2*CB);
            for (int g = tid; g < COUT*8; g += 256) {
                int r = g >> 3, seg = g & 7;
                uint32_t d = bb + r*128 + ((seg ^ (r & 7)) << 4);
                size_t s = ((size_t)(k+1)*COUT + r)*64 + seg*8;
                cpa16(d,      wh + s, 16);
                cpa16(d + CB, wl + s, 16);
            }
            CPA_COMMIT();
        }
        const int pA = p00 + (k/3)*PW + (k%3);
        const uint32_t aBaseH = sb + pA*128;
        const uint32_t aBaseL = sb + BH + pA*128;
        const int aXor = pA & 7;
        const uint32_t bb = sb + oB + (k & 1)*(2*CB);
        #pragma unroll
        for (int ks = 0; ks < 4; ks++) {
            uint32_t ah[4], al[4];
            const uint32_t ao = (uint32_t)(((2*ks + aHalf) ^ aXor) << 4);
            ldsm_x4(ah, aBaseH + ao);
            ldsm_x4(al, aBaseL + ao);
            #pragma unroll
            for (int nb = 0; nb < NB; nb++) {
                const uint32_t bo = bb + (nb*8 + bRow)*128 + (((2*ks + bHalf) ^ bRow) << 4);
                uint32_t bh[2], bl[2];
                ldsm_x2(bh, bo);
                ldsm_x2(bl, bo + CB);
                mma16816(acc[nb], ah, bh);
                mma16816(acc[nb], al, bh);
                mma16816(acc[nb], ah, bl);
            }
        }
    }

    // ---- epilogue: dump -> pool -> bias/relu -> NHWC hi/lo (reuse band smem) ----
    __syncthreads();
    float* so = reinterpret_cast<float*>(smp);
    {
        const int row = wid*16 + (lane >> 2);
        const int col = 2*(lane & 3);
        #pragma unroll
        for (int nb = 0; nb < NB; nb++) {
            so[row*COUT + nb*8 + col]       = acc[nb].x;
            so[row*COUT + nb*8 + col + 1]   = acc[nb].y;
            so[(row+8)*COUT + nb*8 + col]   = acc[nb].z;
            so[(row+8)*COUT + nb*8 + col+1] = acc[nb].w;
        }
    }
    __syncthreads();
    for (int g = tid; g < 32*NB; g += 256) {
        int pp_l = g / NB, cg = g % NB;
        int pp = ppb + pp_l;
        if (pp >= HPO*WPO) continue;
        int co0 = cg*8;
        float v[8];
        #pragma unroll
        for (int j = 0; j < 8; j++) v[j] = -1e30f;
        #pragma unroll
        for (int q = 0; q < 4; q++) {
            const float* rp = &so[(4*pp_l + q)*COUT + co0];
            #pragma unroll
            for (int j = 0; j < 8; j++) v[j] = fmaxf(v[j], rp[j]);
        }
        unsigned short hh[8], ll[8];
        #pragma unroll
        for (int j = 0; j < 8; j++) {
            float t = fmaxf(v[j] + bias[co0 + j], 0.f);
            bf16 h = __float2bfloat16(t);
            hh[j] = __bfloat16_as_ushort(h);
            ll[j] = __bfloat16_as_ushort(__float2bfloat16(t - __bfloat162float(h)));
        }
        size_t base = (((size_t)img*HPO + pp/WPO)*WPO + pp%WPO)*COUT + co0;
        *reinterpret_cast<uint4*>(outh + base) =
            make_uint4(hh[0]|((uint32_t)hh[1]<<16), hh[2]|((uint32_t)hh[3]<<16),
                       hh[4]|((uint32_t)hh[5]<<16), hh[6]|((uint32_t)hh[7]<<16));
        *reinterpret_cast<uint4*>(outl + base) =
            make_uint4(ll[0]|((uint32_t)ll[1]<<16), ll[2]|((uint32_t)ll[3]<<16),
                       ll[4]|((uint32_t)ll[5]<<16), ll[6]|((uint32_t)ll[7]<<16));
    }
}

// ---------- HMMA conv, co-on-M (L4): CIN=128, COUT=512, 10x10 -> 5x5 fp32 NCHW ----------
// Resident pixel tile (15x12 zero-padded, 256B rows); weights double-buffered cp.async.
__global__ void __launch_bounds__(256)
conv_mma_co(const bf16* __restrict__ inh, const bf16* __restrict__ inl,
            const bf16* __restrict__ wh,  const bf16* __restrict__ wl,
            const float* __restrict__ bias, float* __restrict__ outf)
{
    constexpr int NB = 13;                       // N = 104 (4 pad rows)
    constexpr uint32_t PXB = 180*256;            // 15x12 pixel band per buf
    constexpr uint32_t oPxL = PXB, oA = 2*PXB;   // A: 2 bufs x (16KB hi + 16KB lo)

    extern __shared__ char dsm[];
    char* smp = (char*)(((uintptr_t)dsm + 1023) & ~(uintptr_t)1023);
    const uint32_t sb = smem_u32(smp);
    const int tid = threadIdx.x, wid = tid >> 5, lane = tid & 31;
    const int img = blockIdx.z, cob = blockIdx.y * 128;

    const bf16* ih = inh + (size_t)img * 100 * 128;
    const bf16* il = inl + (size_t)img * 100 * 128;

    // ---- stage pixel band once (rows: gy = row-1; zero outside 0..9) ----
    for (int g = tid; g < 180*16; g += 256) {
        int p = g >> 4, seg = g & 15;
        int row = p / 12, col = p % 12;
        int gy = row - 1, gx = col - 1;
        bool ok = (gy >= 0 && gy < 10 && gx >= 0 && gx < 10);
        size_t s = ok ? ((size_t)(gy*10 + gx)*128 + seg*8) : 0;
        uint32_t d = p*256 + ((seg ^ (p & 7)) << 4);
        cpa16(sb + d,        ih + s, ok ? 16 : 0);
        cpa16(sb + oPxL + d, il + s, ok ? 16 : 0);
    }
    CPA_COMMIT();
    // ---- prefetch A iter 0 ----
    {
        const uint32_t ab = sb + oA;
        for (int g = tid; g < 1024; g += 256) {
            int m = g >> 3, seg = g & 7;
            size_t s = ((size_t)cob + m)*64 + seg*8;
            uint32_t d = ab + m*128 + ((seg ^ (m & 7)) << 4);
            cpa16(d,         wh + s, 16);
            cpa16(d + 16384, wl + s, 16);
        }
        CPA_COMMIT();
    }

    float4 acc[NB];
    #pragma unroll
    for (int i = 0; i < NB; i++) acc[i] = make_float4(0,0,0,0);

    const int aRow = wid*16 + (lane & 15);
    const int aXor = aRow & 7, aHalf = lane >> 4;
    const int bRow = lane & 7, bHalf = (lane >> 3) & 1;
    int p00b[NB];
    #pragma unroll
    for (int nb = 0; nb < NB; nb++) {
        int n = nb*8 + bRow;
        int pp = n >> 2, q = n & 3;
        if (pp < 25) {
            int y = 2*(pp/5) + (q >> 1);
            int x = 2*(pp%5) + (q & 1);
            p00b[nb] = (y + 1)*12 + (x + 1);
        } else p00b[nb] = 156;   // always-zero row
    }

    for (int it = 0; it < 18; it++) {
        CPA_WAIT0();
        __syncthreads();
        if (it < 17) {
            int kn = (it+1) >> 1, cn = (it+1) & 1;
            const uint32_t ab = sb + oA + ((it+1) & 1)*32768;
            for (int g = tid; g < 1024; g += 256) {
                int m = g >> 3, seg = g & 7;
                size_t s = ((size_t)(kn*2 + cn)*512 + cob + m)*64 + seg*8;
                uint32_t d = ab + m*128 + ((seg ^ (m & 7)) << 4);
                cpa16(d,         wh + s, 16);
                cpa16(d + 16384, wl + s, 16);
            }
            CPA_COMMIT();
        }
        const int k = it >> 1, cic = it & 1;
        const int dtap = (k/3 - 1)*12 + (k%3 - 1);
        const uint32_t aBase = sb + oA + (it & 1)*32768 + aRow*128;
        #pragma unroll
        for (int ks = 0; ks < 4; ks++) {
            uint32_t ah[4], al[4];
            const uint32_t ao = (uint32_t)(((2*ks + aHalf) ^ aXor) << 4);
            ldsm_x4(ah, aBase + ao);
            ldsm_x4(al, aBase + 16384 + ao);
            #pragma unroll
            for (int nb = 0; nb < NB; nb++) {
                const int pb = p00b[nb] + dtap;
                const uint32_t bo = sb + pb*256 + ((((cic<<3) + 2*ks + bHalf) ^ (pb & 7)) << 4);
                uint32_t bh[2], bl[2];
                ldsm_x2(bh, bo);
                ldsm_x2(bl, bo + oPxL);
                mma16816(acc[nb], ah, bh);
                mma16816(acc[nb], al, bh);
                mma16816(acc[nb], ah, bl);
            }
        }
    }

    __syncthreads();
    float* so = reinterpret_cast<float*>(smp + oA);   // [128 co][104 px]
    {
        const int row = wid*16 + (lane >> 2);
        const int col = 2*(lane & 3);
        #pragma unroll
        for (int nb = 0; nb < NB; nb++) {
            so[row*104 + nb*8 + col]       = acc[nb].x;
            so[row*104 + nb*8 + col + 1]   = acc[nb].y;
            so[(row+8)*104 + nb*8 + col]   = acc[nb].z;
            so[(row+8)*104 + nb*8 + col+1] = acc[nb].w;
        }
    }
    __syncthreads();
    for (int g = tid; g < 3200; g += 256) {
        int co_l = g / 25, pp = g % 25;
        float4 q4 = *reinterpret_cast<float4*>(&so[co_l*104 + 4*pp]);
        float v = fmaxf(fmaxf(q4.x, q4.y), fmaxf(q4.z, q4.w));
        v = fmaxf(v + bias[cob + co_l], 0.f);
        outf[((size_t)img*512 + cob + co_l)*25 + pp] = v;
    }
}

// ---------- prototypes / head / scores ----------
__global__ void proto_kernel(const float* __restrict__ ytr) {
    const int bk = blockIdx.x, b = bk/5, k = bk - b*5, c = threadIdx.x;
    float ssum = 0.f, ysum = 0.f;
    for (int n = 0; n < 25; n++) {
        float y = ytr[(b*25 + n)*5 + k];
        ysum += y;
        if (y != 0.f) {
            const float* fp = &g_f4[((size_t)(b*25 + n)*512 + c)*25];
            float sp = 0.f;
            #pragma unroll
            for (int p = 0; p < 25; p++) sp += fp[p];
            ssum = fmaf(y, sp, ssum);
        }
    }
    float val = ssum / (ysum * 25.f);
    __shared__ float red[512];
    red[c] = val*val; __syncthreads();
    for (int o = 256; o > 0; o >>= 1) { if (c < o) red[c] += red[c+o]; __syncthreads(); }
    g_fa[(size_t)bk*512 + c] = val / fmaxf(sqrtf(red[0]), 1e-12f);
}
__global__ void predict_kernel(const float* __restrict__ wc, const float* __restrict__ bc,
                               float* __restrict__ out) {
    const int q = blockIdx.x, c = threadIdx.x;
    const float* fp = &g_f4[((size_t)(100 + q)*512 + c)*25];
    float s = 0.f;
    #pragma unroll
    for (int p = 0; p < 25; p++) s += fp[p];
    s /= 25.f;
    __shared__ float red[512], sf[512];
    red[c] = s*s; __syncthreads();
    for (int o = 256; o > 0; o >>= 1) { if (c < o) red[c] += red[c+o]; __syncthreads(); }
    sf[c] = s / fmaxf(sqrtf(red[0]), 1e-12f);
    __syncthreads();
    if (c < 64) {
        float a = bc[c];
        const float* wr = &wc[(size_t)c*512];
        #pragma unroll 8
        for (int d = 0; d < 512; d++) a = fmaf(sf[d], wr[d], a);
        out[(size_t)q*64 + c] = a;
    }
}
__global__ void score_kernel(float* __restrict__ out) {
    constexpr int CH = 128;
    __shared__ float sf[CH*25], sfa[5*129], snrm[25];
    const int q = blockIdx.x, b = q/75, tid = threadIdx.x;
    const float* fbase = &g_f4[(size_t)(100 + q)*512*25];
    float acc = 0.f;
    const int di = tid/25, dp = tid%25, pn = tid - 125;
    for (int cb = 0; cb < 4; cb++) {
        __syncthreads();
        for (int i = tid; i < CH*25; i += 256) sf[i] = fbase[cb*CH*25 + i];
        for (int i = tid; i < 5*CH; i += 256) {
            int ii = i/CH, cc = i - ii*CH;
            sfa[ii*129 + cc] = g_fa[((size_t)(b*5 + ii))*512 + cb*CH + cc];
        }
        __syncthreads();
        if (tid < 125) {
            #pragma unroll 4
            for (int c = 0; c < CH; c++) acc = fmaf(sf[c*25 + dp], sfa[di*129 + c], acc);
        } else if (tid < 150) {
            #pragma unroll 4
            for (int c = 0; c < CH; c++) { float v = sf[c*25 + pn]; acc = fmaf(v, v, acc); }
        }
    }
    if (tid >= 125 && tid < 150) snrm[pn] = fmaxf(sqrtf(acc), 1e-12f);
    __syncthreads();
    if (tid < 125) out[(size_t)q*125 + tid] = acc / snrm[dp];
}

// ---------- launch ----------
extern "C" void kernel_launch(void* const* d_in, const int* in_sizes, int n_in,
                              void* d_out, int out_size)
{
    const float* xtr = (const float*)d_in[0];
    const float* xte = (const float*)d_in[1];
    const float* ytr = (const float*)d_in[2];
    const float* w1 = (const float*)d_in[4];  const float* b1 = (const float*)d_in[5];
    const float* w2 = (const float*)d_in[6];  const float* b2 = (const float*)d_in[7];
    const float* w3 = (const float*)d_in[8];  const float* b3 = (const float*)d_in[9];
    const float* w4 = (const float*)d_in[10]; const float* b4 = (const float*)d_in[11];
    const float* wc = (const float*)d_in[12]; const float* bc = (const float*)d_in[13];
    float* out = (float*)d_out;

    float *f4, *w1d;
    bf16 *a1h,*a1l,*a2h,*a2l,*a3h,*a3l,*w2h,*w2l,*w3h,*w3l,*w4h,*w4l;
    cudaGetSymbolAddress((void**)&f4, g_f4);
    cudaGetSymbolAddress((void**)&w1d, g_w1d);
    cudaGetSymbolAddress((void**)&a1h, g_a1h); cudaGetSymbolAddress((void**)&a1l, g_a1l);
    cudaGetSymbolAddress((void**)&a2h, g_a2h); cudaGetSymbolAddress((void**)&a2l, g_a2l);
    cudaGetSymbolAddress((void**)&a3h, g_a3h); cudaGetSymbolAddress((void**)&a3l, g_a3l);
    cudaGetSymbolAddress((void**)&w2h, g_w2h); cudaGetSymbolAddress((void**)&w2l, g_w2l);
    cudaGetSymbolAddress((void**)&w3h, g_w3h); cudaGetSymbolAddress((void**)&w3l, g_w3l);
    cudaGetSymbolAddress((void**)&w4h, g_w4h); cudaGetSymbolAddress((void**)&w4l, g_w4l);

    repack_kernel<<<8, 256>>>(w1, w1d, 3, 64);
    repack_bf16_kernel<<<144, 256>>>(w2, w2h, w2l, 64, 64);
    repack_bf16_kernel<<<288, 256>>>(w3, w3h, w3l, 64, 128);
    repack_bf16_kernel<<<2304, 256>>>(w4, w4h, w4l, 128, 512);

    conv1_kernel<<<dim3(42, 1, 400), 336>>>(xtr, xte, 100, w1d, b1, a1h, a1l);

    {   // L2: 64->64, band 8x44, B dbuf
        auto kfn = conv_mma_px<64, 42, 42, 21, 21, 8, 44>;
        int sm = 1024 + 2*(8*44*128) + 4*(64*128);
        cudaFuncSetAttribute(kfn, cudaFuncAttributeMaxDynamicSharedMemorySize, sm);
        kfn<<<dim3(14, 1, 400), 256, sm>>>(a1h, a1l, w2h, w2l, b2, a2h, a2l);
    }
    {   // L3: 64->128, band 10x28
        auto kfn = conv_mma_px<128, 21, 21, 10, 10, 10, 28>;
        int sm = 1024 + 2*(10*28*128) + 4*(128*128);
        cudaFuncSetAttribute(kfn, cudaFuncAttributeMaxDynamicSharedMemorySize, sm);
        kfn<<<dim3(4, 1, 400), 256, sm>>>(a2h, a2l, w3h, w3l, b3, a3h, a3l);
    }
    {   // L4: 128->512, resident pixels, streamed weights
        int sm = 1024 + 2*(180*256) + 2*32768;
        cudaFuncSetAttribute(conv_mma_co, cudaFuncAttributeMaxDynamicSharedMemorySize, sm);
        conv_mma_co<<<dim3(1, 4, 400), 256, sm>>>(a3h, a3l, w4h, w4l, b4, f4);
    }

    proto_kernel<<<20, 512>>>(ytr);
    predict_kernel<<<300, 512>>>(wc, bc, out);
    score_kernel<<<300, 256>>>(out + 300*64);
}

// round 7
// speedup vs baseline: 3.2096x; 1.1264x over previous
#include <cuda_runtime.h>
#include <cuda_bf16.h>
#include <cstdint>
#include <math.h>

typedef __nv_bfloat16 bf16;
#define ALG __align__(128)

// ---------- scratch ----------
__device__ ALG bf16 g_a1h[400u*42*42*64];
__device__ ALG bf16 g_a1l[400u*42*42*64];
__device__ ALG bf16 g_a2h[400u*21*21*64];
__device__ ALG bf16 g_a2l[400u*21*21*64];
__device__ ALG bf16 g_a3h[400u*10*10*128];
__device__ ALG bf16 g_a3l[400u*10*10*128];
__device__ ALG float g_f4[400u*512*25];
__device__ float g_fa[4u*5*512];
__device__ ALG bf16 g_w1q[64*64];                 // [64 co][hi 32 | lo 32] bf16
__device__ ALG bf16 g_w2h[9*64*64];   __device__ ALG bf16 g_w2l[9*64*64];
__device__ ALG bf16 g_w3h[9*128*64];  __device__ ALG bf16 g_w3l[9*128*64];
__device__ ALG bf16 g_w4h[9*2*512*64];__device__ ALG bf16 g_w4l[9*2*512*64];

// ---------- helpers ----------
__device__ __forceinline__ uint32_t smem_u32(const void* p) {
    uint32_t a;
    asm("{ .reg .u64 t; cvta.to.shared.u64 t, %1; cvt.u32.u64 %0, t; }" : "=r"(a) : "l"(p));
    return a;
}
__device__ __forceinline__ void ldsm_x4(uint32_t* r, uint32_t a) {
    asm volatile("ldmatrix.sync.aligned.m8n8.x4.shared.b16 {%0,%1,%2,%3}, [%4];"
        : "=r"(r[0]), "=r"(r[1]), "=r"(r[2]), "=r"(r[3]) : "r"(a));
}
__device__ __forceinline__ void ldsm_x2(uint32_t* r, uint32_t a) {
    asm volatile("ldmatrix.sync.aligned.m8n8.x2.shared.b16 {%0,%1}, [%2];"
        : "=r"(r[0]), "=r"(r[1]) : "r"(a));
}
__device__ __forceinline__ void mma16816(float4& d, const uint32_t* a, const uint32_t* b) {
    asm volatile("mma.sync.aligned.m16n8k16.row.col.f32.bf16.bf16.f32 "
        "{%0,%1,%2,%3},{%4,%5,%6,%7},{%8,%9},{%0,%1,%2,%3};"
        : "+f"(d.x), "+f"(d.y), "+f"(d.z), "+f"(d.w)
        : "r"(a[0]), "r"(a[1]), "r"(a[2]), "r"(a[3]), "r"(b[0]), "r"(b[1]));
}
__device__ __forceinline__ void cpa16(uint32_t dst, const void* src, int sz) {
    asm volatile("cp.async.cg.shared.global [%0], [%1], 16, %2;"
                 :: "r"(dst), "l"(src), "r"(sz) : "memory");
}
__device__ __forceinline__ void cpa4(uint32_t dst, const void* src, int sz) {
    asm volatile("cp.async.ca.shared.global [%0], [%1], 4, %2;"
                 :: "r"(dst), "l"(src), "r"(sz) : "memory");
}
#define CPA_COMMIT() asm volatile("cp.async.commit_group;" ::: "memory")
#define CPA_WAIT0()  asm volatile("cp.async.wait_group 0;" ::: "memory")

// ---------- weight repacks ----------
__global__ void repack_w1_kernel(const float* __restrict__ w, bf16* __restrict__ o) {
    int i = blockIdx.x*blockDim.x + threadIdx.x;
    if (i >= 64*32) return;
    int co = i >> 5, j = i & 31;
    float v = (j < 27) ? w[co*27 + j] : 0.f;
    bf16 h = __float2bfloat16(v);
    o[co*64 + j]      = h;
    o[co*64 + 32 + j] = __float2bfloat16(v - __bfloat162float(h));
}
__global__ void repack_bf16_kernel(const float* __restrict__ w, bf16* __restrict__ oh,
                                   bf16* __restrict__ ol, int cin, int cout) {
    int nc = cin / 64, total = 9 * nc * cout * 64;
    for (int i = blockIdx.x*blockDim.x + threadIdx.x; i < total; i += gridDim.x*blockDim.x) {
        int cil = i & 63, t = i >> 6;
        int co = t % cout; t /= cout;
        int cic = t % nc;  t /= nc;
        int k = t;
        float v = w[((size_t)co*cin + cic*64 + cil)*9 + k];
        bf16 h = __float2bfloat16(v);
        oh[i] = h; ol[i] = __float2bfloat16(v - __bfloat162float(h));
    }
}

// ---------- L1 as HMMA: im2col K=32 (27 used), pixels-on-M, N=64 ----------
__global__ void __launch_bounds__(256)
conv1_mma(const float* __restrict__ inA, const float* __restrict__ inB, int nsplit,
          const bf16* __restrict__ wq, const float* __restrict__ bias,
          bf16* __restrict__ outh, bf16* __restrict__ outl)
{
    constexpr int HPO = 42, WPO = 42, NPX = 42*42;   // pooled
    constexpr uint32_t oBand = 0, oA = 6400, oB = 6400 + 16384;
    extern __shared__ char dsm[];
    char* smp = (char*)(((uintptr_t)dsm + 1023) & ~(uintptr_t)1023);
    const uint32_t sb = smem_u32(smp);
    float* sband = reinterpret_cast<float*>(smp + oBand);
    const int tid = threadIdx.x, wid = tid >> 5, lane = tid & 31;
    const int img = blockIdx.z, ppb = blockIdx.x * 32;
    const int r0 = ppb / WPO;
    const int ystart = 2*r0 - 1;

    const float* im = (img < nsplit) ? inA + (size_t)img*3*84*84
                                     : inB + (size_t)(img - nsplit)*3*84*84;

    // ---- stage fp32 halo band [3][6][88] (zero padded) ----
    for (int g = tid; g < 3*6*88; g += 256) {
        int ci = g / 528, rem = g - ci*528;
        int row = rem / 88, col = rem - row*88;
        int y = ystart + row, x = col - 1;
        bool ok = (y >= 0 && y < 84 && x >= 0 && x < 84);
        cpa4(sb + oBand + (uint32_t)g*4, im + (ok ? ((size_t)ci*7056 + y*84 + x) : 0), ok ? 4 : 0);
    }
    // ---- stage B weights [64 rows][128B: hi|lo] swizzled ----
    for (int g = tid; g < 64*8; g += 256) {
        int r = g >> 3, seg = g & 7;
        cpa16(sb + oB + r*128 + ((seg ^ (r & 7)) << 4), wq + r*64 + seg*8, 16);
    }
    CPA_COMMIT();
    CPA_WAIT0();
    __syncthreads();

    // ---- build A tile: 128 px rows x [hi 32 | lo 32] bf16, swizzled ----
    {
        const int p = tid >> 1, half = tid & 1;
        const int pp = ppb + (p >> 2), q = p & 3;
        const bool rv = pp < NPX;
        int by0 = 0, bx0 = 0;
        if (rv) {
            int cy = 2*(pp/WPO) + (q >> 1);
            int cx = 2*(pp%WPO) + (q & 1);
            by0 = cy - 1 - ystart;    // 0..3
            bx0 = cx;                 // band col of (cx-1+kx) = cx+kx
        }
        unsigned short hv[16], lv[16];
        #pragma unroll
        for (int j = 0; j < 16; j++) { hv[j] = 0; lv[j] = 0; }
        #pragma unroll
        for (int ci = 0; ci < 3; ci++)
            #pragma unroll
            for (int tap = 0; tap < 9; tap++) {
                constexpr int unused = 0; (void)unused;
                int j = ci*9 + tap;
                if ((j >> 4) != half) continue;
                float v = rv ? sband[(ci*6 + by0 + tap/3)*88 + bx0 + tap%3] : 0.f;
                bf16 h = __float2bfloat16(v);
                hv[j & 15] = __bfloat16_as_ushort(h);
                lv[j & 15] = __bfloat16_as_ushort(__float2bfloat16(v - __bfloat162float(h)));
            }
        uint32_t hw[8], lw[8];
        #pragma unroll
        for (int c = 0; c < 8; c++) {
            hw[c] = hv[2*c] | ((uint32_t)hv[2*c+1] << 16);
            lw[c] = lv[2*c] | ((uint32_t)lv[2*c+1] << 16);
        }
        const uint32_t rb = sb + oA + p*128;
        const int px = p & 7;
        *reinterpret_cast<uint4*>((char*)0 + rb + (((half*2 + 0) ^ px) << 4)) = make_uint4(hw[0],hw[1],hw[2],hw[3]);
        // (can't deref smem uint32 addr as pointer portably; use asm stores below instead)
        (void)lw;
        asm volatile("st.shared.v4.b32 [%0], {%1,%2,%3,%4};" :: "r"(rb + (((half*2 + 0) ^ px) << 4)),
                     "r"(hw[0]), "r"(hw[1]), "r"(hw[2]), "r"(hw[3]));
        asm volatile("st.shared.v4.b32 [%0], {%1,%2,%3,%4};" :: "r"(rb + (((half*2 + 1) ^ px) << 4)),
                     "r"(hw[4]), "r"(hw[5]), "r"(hw[6]), "r"(hw[7]));
        asm volatile("st.shared.v4.b32 [%0], {%1,%2,%3,%4};" :: "r"(rb + (((4 + half*2 + 0) ^ px) << 4)),
                     "r"(lw[0]), "r"(lw[1]), "r"(lw[2]), "r"(lw[3]));
        asm volatile("st.shared.v4.b32 [%0], {%1,%2,%3,%4};" :: "r"(rb + (((4 + half*2 + 1) ^ px) << 4)),
                     "r"(lw[4]), "r"(lw[5]), "r"(lw[6]), "r"(lw[7]));
    }
    __syncthreads();

    // ---- MMA: 2 K-steps x 8 N-blocks x 3 passes ----
    float4 acc[8];
    #pragma unroll
    for (int i = 0; i < 8; i++) acc[i] = make_float4(0,0,0,0);
    const int aRow = wid*16 + (lane & 15);
    const int aXor = aRow & 7, aHalf = lane >> 4;
    const int bRow = lane & 7, bHalf = (lane >> 3) & 1;
    #pragma unroll
    for (int ks = 0; ks < 2; ks++) {
        uint32_t ah[4], al[4];
        const uint32_t ab = sb + oA + aRow*128;
        ldsm_x4(ah, ab + (((2*ks + aHalf) ^ aXor) << 4));
        ldsm_x4(al, ab + (((4 + 2*ks + aHalf) ^ aXor) << 4));
        #pragma unroll
        for (int nb = 0; nb < 8; nb++) {
            const uint32_t bb = sb + oB + (nb*8 + bRow)*128;
            uint32_t bh[2], bl[2];
            ldsm_x2(bh, bb + (((2*ks + bHalf) ^ bRow) << 4));
            ldsm_x2(bl, bb + (((4 + 2*ks + bHalf) ^ bRow) << 4));
            mma16816(acc[nb], ah, bh);
            mma16816(acc[nb], al, bh);
            mma16816(acc[nb], ah, bl);
        }
    }

    // ---- epilogue: dump -> pool -> bias/relu -> NHWC hi/lo ----
    __syncthreads();
    float* so = reinterpret_cast<float*>(smp);
    {
        const int row = wid*16 + (lane >> 2);
        const int col = 2*(lane & 3);
        #pragma unroll
        for (int nb = 0; nb < 8; nb++) {
            so[row*64 + nb*8 + col]       = acc[nb].x;
            so[row*64 + nb*8 + col + 1]   = acc[nb].y;
            so[(row+8)*64 + nb*8 + col]   = acc[nb].z;
            so[(row+8)*64 + nb*8 + col+1] = acc[nb].w;
        }
    }
    __syncthreads();
    for (int g = tid; g < 32*8; g += 256) {
        int pp_l = g >> 3, cg = g & 7;
        int pp = ppb + pp_l;
        if (pp >= NPX) continue;
        int co0 = cg*8;
        float v[8];
        #pragma unroll
        for (int j = 0; j < 8; j++) v[j] = -1e30f;
        #pragma unroll
        for (int q = 0; q < 4; q++) {
            const float* rp = &so[(4*pp_l + q)*64 + co0];
            #pragma unroll
            for (int j = 0; j < 8; j++) v[j] = fmaxf(v[j], rp[j]);
        }
        unsigned short hh[8], ll[8];
        #pragma unroll
        for (int j = 0; j < 8; j++) {
            float t = fmaxf(v[j] + bias[co0 + j], 0.f);
            bf16 h = __float2bfloat16(t);
            hh[j] = __bfloat16_as_ushort(h);
            ll[j] = __bfloat16_as_ushort(__float2bfloat16(t - __bfloat162float(h)));
        }
        size_t base = (((size_t)img*HPO + pp/WPO)*WPO + pp%WPO)*64 + co0;
        *reinterpret_cast<uint4*>(outh + base) =
            make_uint4(hh[0]|((uint32_t)hh[1]<<16), hh[2]|((uint32_t)hh[3]<<16),
                       hh[4]|((uint32_t)hh[5]<<16), hh[6]|((uint32_t)hh[7]<<16));
        *reinterpret_cast<uint4*>(outl + base) =
            make_uint4(ll[0]|((uint32_t)ll[1]<<16), ll[2]|((uint32_t)ll[3]<<16),
                       ll[4]|((uint32_t)ll[5]<<16), ll[6]|((uint32_t)ll[7]<<16));
    }
}

// ---------- HMMA conv, pixels-on-M (L2, L3): CIN=64 ----------
template<int COUT, int HIN, int WIN, int HPO, int WPO, int NROWS, int PW>
__global__ void __launch_bounds__(256)
conv_mma_px(const bf16* __restrict__ inh, const bf16* __restrict__ inl,
            const bf16* __restrict__ wh,  const bf16* __restrict__ wl,
            const float* __restrict__ bias,
            bf16* __restrict__ outh, bf16* __restrict__ outl)
{
    constexpr int NB = COUT/8;
    constexpr int BANDPX = NROWS*PW;
    constexpr uint32_t BH = BANDPX*128;
    constexpr uint32_t CB = COUT*128;
    constexpr uint32_t oB = 2*BH;

    extern __shared__ char dsm[];
    char* smp = (char*)(((uintptr_t)dsm + 1023) & ~(uintptr_t)1023);
    const uint32_t sb = smem_u32(smp);
    const int tid = threadIdx.x, wid = tid >> 5, lane = tid & 31;
    const int img = blockIdx.z, ppb = blockIdx.x * 32;
    const int r0 = ppb / WPO;
    const int ystart = 2*r0 - 1;

    const bf16* ih = inh + (size_t)img * HIN * WIN * 64;
    const bf16* il = inl + (size_t)img * HIN * WIN * 64;

    for (int g = tid; g < BANDPX*8; g += 256) {
        int p = g >> 3, seg = g & 7;
        int row = p / PW, col = p % PW;
        int gy = ystart + row, gx = col - 1;
        bool ok = (gy >= 0 && gy < HIN && gx >= 0 && gx < WIN);
        size_t s = ok ? (((size_t)gy*WIN + gx)*64 + seg*8) : 0;
        uint32_t d = p*128 + ((seg ^ (p & 7)) << 4);
        cpa16(sb + d,      ih + s, ok ? 16 : 0);
        cpa16(sb + BH + d, il + s, ok ? 16 : 0);
    }
    CPA_COMMIT();
    {
        const uint32_t bb = sb + oB;
        for (int g = tid; g < COUT*8; g += 256) {
            int r = g >> 3, seg = g & 7;
            uint32_t d = bb + r*128 + ((seg ^ (r & 7)) << 4);
            size_t s = (size_t)r*64 + seg*8;
            cpa16(d,      wh + s, 16);
            cpa16(d + CB, wl + s, 16);
        }
        CPA_COMMIT();
    }

    float4 acc[NB];
    #pragma unroll
    for (int i = 0; i < NB; i++) acc[i] = make_float4(0,0,0,0);

    const int aRow = wid*16 + (lane & 15);
    const int appd = aRow >> 2, aq = aRow & 3;
    const int ay = 2*((ppb + appd)/WPO) + (aq >> 1);
    const int ax = 2*((ppb + appd)%WPO) + (aq & 1);
    const int p00 = (ay - 2*r0)*PW + ax;
    const int aHalf = lane >> 4;
    const int bRow = lane & 7, bHalf = (lane >> 3) & 1;

    for (int k = 0; k < 9; k++) {
        CPA_WAIT0();
        __syncthreads();
        if (k < 8) {
            const uint32_t bb = sb + oB + ((k+1) & 1)*(2*CB);
            for (int g = tid; g < COUT*8; g += 256) {
                int r = g >> 3, seg = g & 7;
                uint32_t d = bb + r*128 + ((seg ^ (r & 7)) << 4);
                size_t s = ((size_t)(k+1)*COUT + r)*64 + seg*8;
                cpa16(d,      wh + s, 16);
                cpa16(d + CB, wl + s, 16);
            }
            CPA_COMMIT();
        }
        const int pA = p00 + (k/3)*PW + (k%3);
        const uint32_t aBaseH = sb + pA*128;
        const uint32_t aBaseL = sb + BH + pA*128;
        const int aXor = pA & 7;
        const uint32_t bb = sb + oB + (k & 1)*(2*CB);
        #pragma unroll
        for (int ks = 0; ks < 4; ks++) {
            uint32_t ah[4], al[4];
            const uint32_t ao = (uint32_t)(((2*ks + aHalf) ^ aXor) << 4);
            ldsm_x4(ah, aBaseH + ao);
            ldsm_x4(al, aBaseL + ao);
            #pragma unroll
            for (int nb = 0; nb < NB; nb++) {
                const uint32_t bo = bb + (nb*8 + bRow)*128 + (((2*ks + bHalf) ^ bRow) << 4);
                uint32_t bh[2], bl[2];
                ldsm_x2(bh, bo);
                ldsm_x2(bl, bo + CB);
                mma16816(acc[nb], ah, bh);
                mma16816(acc[nb], al, bh);
                mma16816(acc[nb], ah, bl);
            }
        }
    }

    __syncthreads();
    float* so = reinterpret_cast<float*>(smp);
    {
        const int row = wid*16 + (lane >> 2);
        const int col = 2*(lane & 3);
        #pragma unroll
        for (int nb = 0; nb < NB; nb++) {
            so[row*COUT + nb*8 + col]       = acc[nb].x;
            so[row*COUT + nb*8 + col + 1]   = acc[nb].y;
            so[(row+8)*COUT + nb*8 + col]   = acc[nb].z;
            so[(row+8)*COUT + nb*8 + col+1] = acc[nb].w;
        }
    }
    __syncthreads();
    for (int g = tid; g < 32*NB; g += 256) {
        int pp_l = g / NB, cg = g % NB;
        int pp = ppb + pp_l;
        if (pp >= HPO*WPO) continue;
        int co0 = cg*8;
        float v[8];
        #pragma unroll
        for (int j = 0; j < 8; j++) v[j] = -1e30f;
        #pragma unroll
        for (int q = 0; q < 4; q++) {
            const float* rp = &so[(4*pp_l + q)*COUT + co0];
            #pragma unroll
            for (int j = 0; j < 8; j++) v[j] = fmaxf(v[j], rp[j]);
        }
        unsigned short hh[8], ll[8];
        #pragma unroll
        for (int j = 0; j < 8; j++) {
            float t = fmaxf(v[j] + bias[co0 + j], 0.f);
            bf16 h = __float2bfloat16(t);
            hh[j] = __bfloat16_as_ushort(h);
            ll[j] = __bfloat16_as_ushort(__float2bfloat16(t - __bfloat162float(h)));
        }
        size_t base = (((size_t)img*HPO + pp/WPO)*WPO + pp%WPO)*COUT + co0;
        *reinterpret_cast<uint4*>(outh + base) =
            make_uint4(hh[0]|((uint32_t)hh[1]<<16), hh[2]|((uint32_t)hh[3]<<16),
                       hh[4]|((uint32_t)hh[5]<<16), hh[6]|((uint32_t)hh[7]<<16));
        *reinterpret_cast<uint4*>(outl + base) =
            make_uint4(ll[0]|((uint32_t)ll[1]<<16), ll[2]|((uint32_t)ll[3]<<16),
                       ll[4]|((uint32_t)ll[5]<<16), ll[6]|((uint32_t)ll[7]<<16));
    }
}

// ---------- HMMA conv, co-on-M (L4) ----------
__global__ void __launch_bounds__(256)
conv_mma_co(const bf16* __restrict__ inh, const bf16* __restrict__ inl,
            const bf16* __restrict__ wh,  const bf16* __restrict__ wl,
            const float* __restrict__ bias, float* __restrict__ outf)
{
    constexpr int NB = 13;
    constexpr uint32_t PXB = 180*256;
    constexpr uint32_t oPxL = PXB, oA = 2*PXB;

    extern __shared__ char dsm[];
    char* smp = (char*)(((uintptr_t)dsm + 1023) & ~(uintptr_t)1023);
    const uint32_t sb = smem_u32(smp);
    const int tid = threadIdx.x, wid = tid >> 5, lane = tid & 31;
    const int img = blockIdx.z, cob = blockIdx.y * 128;

    const bf16* ih = inh + (size_t)img * 100 * 128;
    const bf16* il = inl + (size_t)img * 100 * 128;

    for (int g = tid; g < 180*16; g += 256) {
        int p = g >> 4, seg = g & 15;
        int row = p / 12, col = p % 12;
        int gy = row - 1, gx = col - 1;
        bool ok = (gy >= 0 && gy < 10 && gx >= 0 && gx < 10);
        size_t s = ok ? ((size_t)(gy*10 + gx)*128 + seg*8) : 0;
        uint32_t d = p*256 + ((seg ^ (p & 7)) << 4);
        cpa16(sb + d,        ih + s, ok ? 16 : 0);
        cpa16(sb + oPxL + d, il + s, ok ? 16 : 0);
    }
    CPA_COMMIT();
    {
        const uint32_t ab = sb + oA;
        for (int g = tid; g < 1024; g += 256) {
            int m = g >> 3, seg = g & 7;
            size_t s = ((size_t)cob + m)*64 + seg*8;
            uint32_t d = ab + m*128 + ((seg ^ (m & 7)) << 4);
            cpa16(d,         wh + s, 16);
            cpa16(d + 16384, wl + s, 16);
        }
        CPA_COMMIT();
    }

    float4 acc[NB];
    #pragma unroll
    for (int i = 0; i < NB; i++) acc[i] = make_float4(0,0,0,0);

    const int aRow = wid*16 + (lane & 15);
    const int aXor = aRow & 7, aHalf = lane >> 4;
    const int bRow = lane & 7, bHalf = (lane >> 3) & 1;
    int p00b[NB];
    #pragma unroll
    for (int nb = 0; nb < NB; nb++) {
        int n = nb*8 + bRow;
        int pp = n >> 2, q = n & 3;
        if (pp < 25) {
            int y = 2*(pp/5) + (q >> 1);
            int x = 2*(pp%5) + (q & 1);
            p00b[nb] = (y + 1)*12 + (x + 1);
        } else p00b[nb] = 156;
    }

    for (int it = 0; it < 18; it++) {
        CPA_WAIT0();
        __syncthreads();
        if (it < 17) {
            int kn = (it+1) >> 1, cn = (it+1) & 1;
            const uint32_t ab = sb + oA + ((it+1) & 1)*32768;
            for (int g = tid; g < 1024; g += 256) {
                int m = g >> 3, seg = g & 7;
                size_t s = ((size_t)(kn*2 + cn)*512 + cob + m)*64 + seg*8;
                uint32_t d = ab + m*128 + ((seg ^ (m & 7)) << 4);
                cpa16(d,         wh + s, 16);
                cpa16(d + 16384, wl + s, 16);
            }
            CPA_COMMIT();
        }
        const int k = it >> 1, cic = it & 1;
        const int dtap = (k/3 - 1)*12 + (k%3 - 1);
        const uint32_t aBase = sb + oA + (it & 1)*32768 + aRow*128;
        #pragma unroll
        for (int ks = 0; ks < 4; ks++) {
            uint32_t ah[4], al[4];
            const uint32_t ao = (uint32_t)(((2*ks + aHalf) ^ aXor) << 4);
            ldsm_x4(ah, aBase + ao);
            ldsm_x4(al, aBase + 16384 + ao);
            #pragma unroll
            for (int nb = 0; nb < NB; nb++) {
                const int pb = p00b[nb] + dtap;
                const uint32_t bo = sb + pb*256 + ((((cic<<3) + 2*ks + bHalf) ^ (pb & 7)) << 4);
                uint32_t bh[2], bl[2];
                ldsm_x2(bh, bo);
                ldsm_x2(bl, bo + oPxL);
                mma16816(acc[nb], ah, bh);
                mma16816(acc[nb], al, bh);
                mma16816(acc[nb], ah, bl);
            }
        }
    }

    __syncthreads();
    float* so = reinterpret_cast<float*>(smp + oA);
    {
        const int row = wid*16 + (lane >> 2);
        const int col = 2*(lane & 3);
        #pragma unroll
        for (int nb = 0; nb < NB; nb++) {
            so[row*104 + nb*8 + col]       = acc[nb].x;
            so[row*104 + nb*8 + col + 1]   = acc[nb].y;
            so[(row+8)*104 + nb*8 + col]   = acc[nb].z;
            so[(row+8)*104 + nb*8 + col+1] = acc[nb].w;
        }
    }
    __syncthreads();
    for (int g = tid; g < 3200; g += 256) {
        int co_l = g / 25, pp = g % 25;
        float4 q4 = *reinterpret_cast<float4*>(&so[co_l*104 + 4*pp]);
        float v = fmaxf(fmaxf(q4.x, q4.y), fmaxf(q4.z, q4.w));
        v = fmaxf(v + bias[cob + co_l], 0.f);
        outf[((size_t)img*512 + cob + co_l)*25 + pp] = v;
    }
}

// ---------- prototypes / head / scores ----------
__global__ void proto_kernel(const float* __restrict__ ytr) {
    const int bk = blockIdx.x, b = bk/5, k = bk - b*5, c = threadIdx.x;
    float ssum = 0.f, ysum = 0.f;
    for (int n = 0; n < 25; n++) {
        float y = ytr[(b*25 + n)*5 + k];
        ysum += y;
        if (y != 0.f) {
            const float* fp = &g_f4[((size_t)(b*25 + n)*512 + c)*25];
            float sp = 0.f;
            #pragma unroll
            for (int p = 0; p < 25; p++) sp += fp[p];
            ssum = fmaf(y, sp, ssum);
        }
    }
    float val = ssum / (ysum * 25.f);
    __shared__ float red[512];
    red[c] = val*val; __syncthreads();
    for (int o = 256; o > 0; o >>= 1) { if (c < o) red[c] += red[c+o]; __syncthreads(); }
    g_fa[(size_t)bk*512 + c] = val / fmaxf(sqrtf(red[0]), 1e-12f);
}
__global__ void predict_kernel(const float* __restrict__ wc, const float* __restrict__ bc,
                               float* __restrict__ out) {
    const int q = blockIdx.x, c = threadIdx.x;
    const float* fp = &g_f4[((size_t)(100 + q)*512 + c)*25];
    float s = 0.f;
    #pragma unroll
    for (int p = 0; p < 25; p++) s += fp[p];
    s /= 25.f;
    __shared__ float red[512], sf[512];
    red[c] = s*s; __syncthreads();
    for (int o = 256; o > 0; o >>= 1) { if (c < o) red[c] += red[c+o]; __syncthreads(); }
    sf[c] = s / fmaxf(sqrtf(red[0]), 1e-12f);
    __syncthreads();
    if (c < 64) {
        float a = bc[c];
        const float* wr = &wc[(size_t)c*512];
        #pragma unroll 8
        for (int d = 0; d < 512; d++) a = fmaf(sf[d], wr[d], a);
        out[(size_t)q*64 + c] = a;
    }
}
__global__ void score_kernel(float* __restrict__ out) {
    constexpr int CH = 128;
    __shared__ float sf[CH*25], sfa[5*129], snrm[25];
    const int q = blockIdx.x, b = q/75, tid = threadIdx.x;
    const float* fbase = &g_f4[(size_t)(100 + q)*512*25];
    float acc = 0.f;
    const int di = tid/25, dp = tid%25, pn = tid - 125;
    for (int cb = 0; cb < 4; cb++) {
        __syncthreads();
        for (int i = tid; i < CH*25; i += 256) sf[i] = fbase[cb*CH*25 + i];
        for (int i = tid; i < 5*CH; i += 256) {
            int ii = i/CH, cc = i - ii*CH;
            sfa[ii*129 + cc] = g_fa[((size_t)(b*5 + ii))*512 + cb*CH + cc];
        }
        __syncthreads();
        if (tid < 125) {
            #pragma unroll 4
            for (int c = 0; c < CH; c++) acc = fmaf(sf[c*25 + dp], sfa[di*129 + c], acc);
        } else if (tid < 150) {
            #pragma unroll 4
            for (int c = 0; c < CH; c++) { float v = sf[c*25 + pn]; acc = fmaf(v, v, acc); }
        }
    }
    if (tid >= 125 && tid < 150) snrm[pn] = fmaxf(sqrtf(acc), 1e-12f);
    __syncthreads();
    if (tid < 125) out[(size_t)q*125 + tid] = acc / snrm[dp];
}

// ---------- launch ----------
extern "C" void kernel_launch(void* const* d_in, const int* in_sizes, int n_in,
                              void* d_out, int out_size)
{
    const float* xtr = (const float*)d_in[0];
    const float* xte = (const float*)d_in[1];
    const float* ytr = (const float*)d_in[2];
    const float* w1 = (const float*)d_in[4];  const float* b1 = (const float*)d_in[5];
    const float* w2 = (const float*)d_in[6];  const float* b2 = (const float*)d_in[7];
    const float* w3 = (const float*)d_in[8];  const float* b3 = (const float*)d_in[9];
    const float* w4 = (const float*)d_in[10]; const float* b4 = (const float*)d_in[11];
    const float* wc = (const float*)d_in[12]; const float* bc = (const float*)d_in[13];
    float* out = (float*)d_out;

    float *f4;
    bf16 *a1h,*a1l,*a2h,*a2l,*a3h,*a3l,*w1q,*w2h,*w2l,*w3h,*w3l,*w4h,*w4l;
    cudaGetSymbolAddress((void**)&f4, g_f4);
    cudaGetSymbolAddress((void**)&w1q, g_w1q);
    cudaGetSymbolAddress((void**)&a1h, g_a1h); cudaGetSymbolAddress((void**)&a1l, g_a1l);
    cudaGetSymbolAddress((void**)&a2h, g_a2h); cudaGetSymbolAddress((void**)&a2l, g_a2l);
    cudaGetSymbolAddress((void**)&a3h, g_a3h); cudaGetSymbolAddress((void**)&a3l, g_a3l);
    cudaGetSymbolAddress((void**)&w2h, g_w2h); cudaGetSymbolAddress((void**)&w2l, g_w2l);
    cudaGetSymbolAddress((void**)&w3h, g_w3h); cudaGetSymbolAddress((void**)&w3l, g_w3l);
    cudaGetSymbolAddress((void**)&w4h, g_w4h); cudaGetSymbolAddress((void**)&w4l, g_w4l);

    repack_w1_kernel<<<8, 256>>>(w1, w1q);
    repack_bf16_kernel<<<144, 256>>>(w2, w2h, w2l, 64, 64);
    repack_bf16_kernel<<<288, 256>>>(w3, w3h, w3l, 64, 128);
    repack_bf16_kernel<<<2304, 256>>>(w4, w4h, w4l, 128, 512);

    {   // L1 HMMA: 56 px-tiles x 400 imgs
        int sm = 33792;
        cudaFuncSetAttribute(conv1_mma, cudaFuncAttributeMaxDynamicSharedMemorySize, sm);
        conv1_mma<<<dim3(56, 1, 400), 256, sm>>>(xtr, xte, 100, w1q, b1, a1h, a1l);
    }
    {   // L2: 64->64, band 8x44, B dbuf
        auto kfn = conv_mma_px<64, 42, 42, 21, 21, 8, 44>;
        int sm = 1024 + 2*(8*44*128) + 4*(64*128);
        cudaFuncSetAttribute(kfn, cudaFuncAttributeMaxDynamicSharedMemorySize, sm);
        kfn<<<dim3(14, 1, 400), 256, sm>>>(a1h, a1l, w2h, w2l, b2, a2h, a2l);
    }
    {   // L3: 64->128, band 10x28
        auto kfn = conv_mma_px<128, 21, 21, 10, 10, 10, 28>;
        int sm = 1024 + 2*(10*28*128) + 4*(128*128);
        cudaFuncSetAttribute(kfn, cudaFuncAttributeMaxDynamicSharedMemorySize, sm);
        kfn<<<dim3(4, 1, 400), 256, sm>>>(a2h, a2l, w3h, w3l, b3, a3h, a3l);
    }
    {   // L4: 128->512
        int sm = 1024 + 2*(180*256) + 2*32768;
        cudaFuncSetAttribute(conv_mma_co, cudaFuncAttributeMaxDynamicSharedMemorySize, sm);
        conv_mma_co<<<dim3(1, 4, 400), 256, sm>>>(a3h, a3l, w4h, w4l, b4, f4);
    }

    proto_kernel<<<20, 512>>>(ytr);
    predict_kernel<<<300, 512>>>(wc, bc, out);
    score_kernel<<<300, 256>>>(out + 300*64);
}

// round 8
// speedup vs baseline: 3.4691x; 1.0809x over previous
#include <cuda_runtime.h>
#include <cuda_bf16.h>
#include <cstdint>
#include <math.h>

typedef __nv_bfloat16 bf16;
#define ALG __align__(128)

// ---------- scratch ----------
__device__ ALG bf16 g_a1h[400u*42*42*64];
__device__ ALG bf16 g_a1l[400u*42*42*64];
__device__ ALG bf16 g_a2h[400u*21*21*64];
__device__ ALG bf16 g_a2l[400u*21*21*64];
__device__ ALG bf16 g_a3h[400u*10*10*128];
__device__ ALG bf16 g_a3l[400u*10*10*128];
__device__ ALG float g_f4[400u*512*25];
__device__ float g_fa[4u*5*512];
__device__ ALG bf16 g_w1q[64*64];
__device__ ALG bf16 g_w2h[9*64*64];   __device__ ALG bf16 g_w2l[9*64*64];
__device__ ALG bf16 g_w3h[9*128*64];  __device__ ALG bf16 g_w3l[9*128*64];
__device__ ALG bf16 g_w4h[9*2*512*64];__device__ ALG bf16 g_w4l[9*2*512*64];

// ---------- helpers ----------
__device__ __forceinline__ uint32_t smem_u32(const void* p) {
    uint32_t a;
    asm("{ .reg .u64 t; cvta.to.shared.u64 t, %1; cvt.u32.u64 %0, t; }" : "=r"(a) : "l"(p));
    return a;
}
__device__ __forceinline__ void ldsm_x4(uint32_t* r, uint32_t a) {
    asm volatile("ldmatrix.sync.aligned.m8n8.x4.shared.b16 {%0,%1,%2,%3}, [%4];"
        : "=r"(r[0]), "=r"(r[1]), "=r"(r[2]), "=r"(r[3]) : "r"(a));
}
__device__ __forceinline__ void ldsm_x2(uint32_t* r, uint32_t a) {
    asm volatile("ldmatrix.sync.aligned.m8n8.x2.shared.b16 {%0,%1}, [%2];"
        : "=r"(r[0]), "=r"(r[1]) : "r"(a));
}
__device__ __forceinline__ void mma16816(float4& d, const uint32_t* a, const uint32_t* b) {
    asm volatile("mma.sync.aligned.m16n8k16.row.col.f32.bf16.bf16.f32 "
        "{%0,%1,%2,%3},{%4,%5,%6,%7},{%8,%9},{%0,%1,%2,%3};"
        : "+f"(d.x), "+f"(d.y), "+f"(d.z), "+f"(d.w)
        : "r"(a[0]), "r"(a[1]), "r"(a[2]), "r"(a[3]), "r"(b[0]), "r"(b[1]));
}
__device__ __forceinline__ void cpa16(uint32_t dst, const void* src, int sz) {
    asm volatile("cp.async.cg.shared.global [%0], [%1], 16, %2;"
                 :: "r"(dst), "l"(src), "r"(sz) : "memory");
}
__device__ __forceinline__ void cpa4(uint32_t dst, const void* src, int sz) {
    asm volatile("cp.async.ca.shared.global [%0], [%1], 4, %2;"
                 :: "r"(dst), "l"(src), "r"(sz) : "memory");
}
#define CPA_COMMIT() asm volatile("cp.async.commit_group;" ::: "memory")
#define CPA_WAIT0()  asm volatile("cp.async.wait_group 0;" ::: "memory")

// ---------- weight repacks ----------
__global__ void repack_w1_kernel(const float* __restrict__ w, bf16* __restrict__ o) {
    int i = blockIdx.x*blockDim.x + threadIdx.x;
    if (i >= 64*32) return;
    int co = i >> 5, j = i & 31;
    float v = (j < 27) ? w[co*27 + j] : 0.f;
    bf16 h = __float2bfloat16(v);
    o[co*64 + j]      = h;
    o[co*64 + 32 + j] = __float2bfloat16(v - __bfloat162float(h));
}
__global__ void repack_bf16_kernel(const float* __restrict__ w, bf16* __restrict__ oh,
                                   bf16* __restrict__ ol, int cin, int cout) {
    int nc = cin / 64, total = 9 * nc * cout * 64;
    for (int i = blockIdx.x*blockDim.x + threadIdx.x; i < total; i += gridDim.x*blockDim.x) {
        int cil = i & 63, t = i >> 6;
        int co = t % cout; t /= cout;
        int cic = t % nc;  t /= nc;
        int k = t;
        float v = w[((size_t)co*cin + cic*64 + cil)*9 + k];
        bf16 h = __float2bfloat16(v);
        oh[i] = h; ol[i] = __float2bfloat16(v - __bfloat162float(h));
    }
}

// ---------- L1 as HMMA: im2col K=32 (27 used), pixels-on-M, N=64 ----------
__global__ void __launch_bounds__(256)
conv1_mma(const float* __restrict__ inA, const float* __restrict__ inB, int nsplit,
          const bf16* __restrict__ wq, const float* __restrict__ bias,
          bf16* __restrict__ outh, bf16* __restrict__ outl)
{
    constexpr int HPO = 42, WPO = 42, NPX = 42*42;
    constexpr uint32_t oBand = 0, oA = 6400, oB = 6400 + 16384;
    extern __shared__ char dsm[];
    char* smp = (char*)(((uintptr_t)dsm + 1023) & ~(uintptr_t)1023);
    const uint32_t sb = smem_u32(smp);
    float* sband = reinterpret_cast<float*>(smp + oBand);
    const int tid = threadIdx.x, wid = tid >> 5, lane = tid & 31;
    const int img = blockIdx.z, ppb = blockIdx.x * 32;
    const int r0 = ppb / WPO;
    const int ystart = 2*r0 - 1;

    const float* im = (img < nsplit) ? inA + (size_t)img*3*84*84
                                     : inB + (size_t)(img - nsplit)*3*84*84;

    for (int g = tid; g < 3*6*88; g += 256) {
        int ci = g / 528, rem = g - ci*528;
        int row = rem / 88, col = rem - row*88;
        int y = ystart + row, x = col - 1;
        bool ok = (y >= 0 && y < 84 && x >= 0 && x < 84);
        cpa4(sb + oBand + (uint32_t)g*4, im + (ok ? ((size_t)ci*7056 + y*84 + x) : 0), ok ? 4 : 0);
    }
    for (int g = tid; g < 64*8; g += 256) {
        int r = g >> 3, seg = g & 7;
        cpa16(sb + oB + r*128 + ((seg ^ (r & 7)) << 4), wq + r*64 + seg*8, 16);
    }
    CPA_COMMIT();
    CPA_WAIT0();
    __syncthreads();

    // build A tile: 128 px rows x [hi 32 | lo 32] bf16, swizzled
    {
        const int p = tid >> 1, half = tid & 1;
        const int pp = ppb + (p >> 2), q = p & 3;
        const bool rv = pp < NPX;
        int by0 = 0, bx0 = 0;
        if (rv) {
            int cy = 2*(pp/WPO) + (q >> 1);
            int cx = 2*(pp%WPO) + (q & 1);
            by0 = cy - 1 - ystart;
            bx0 = cx;
        }
        unsigned short hv[16], lv[16];
        #pragma unroll
        for (int j = 0; j < 16; j++) { hv[j] = 0; lv[j] = 0; }
        #pragma unroll
        for (int ci = 0; ci < 3; ci++)
            #pragma unroll
            for (int tap = 0; tap < 9; tap++) {
                int j = ci*9 + tap;
                if ((j >> 4) != half) continue;
                float v = rv ? sband[(ci*6 + by0 + tap/3)*88 + bx0 + tap%3] : 0.f;
                bf16 h = __float2bfloat16(v);
                hv[j & 15] = __bfloat16_as_ushort(h);
                lv[j & 15] = __bfloat16_as_ushort(__float2bfloat16(v - __bfloat162float(h)));
            }
        uint32_t hw[8], lw[8];
        #pragma unroll
        for (int c = 0; c < 8; c++) {
            hw[c] = hv[2*c] | ((uint32_t)hv[2*c+1] << 16);
            lw[c] = lv[2*c] | ((uint32_t)lv[2*c+1] << 16);
        }
        const uint32_t rb = sb + oA + p*128;
        const int px = p & 7;
        asm volatile("st.shared.v4.b32 [%0], {%1,%2,%3,%4};" :: "r"(rb + (((half*2 + 0) ^ px) << 4)),
                     "r"(hw[0]), "r"(hw[1]), "r"(hw[2]), "r"(hw[3]));
        asm volatile("st.shared.v4.b32 [%0], {%1,%2,%3,%4};" :: "r"(rb + (((half*2 + 1) ^ px) << 4)),
                     "r"(hw[4]), "r"(hw[5]), "r"(hw[6]), "r"(hw[7]));
        asm volatile("st.shared.v4.b32 [%0], {%1,%2,%3,%4};" :: "r"(rb + (((4 + half*2 + 0) ^ px) << 4)),
                     "r"(lw[0]), "r"(lw[1]), "r"(lw[2]), "r"(lw[3]));
        asm volatile("st.shared.v4.b32 [%0], {%1,%2,%3,%4};" :: "r"(rb + (((4 + half*2 + 1) ^ px) << 4)),
                     "r"(lw[4]), "r"(lw[5]), "r"(lw[6]), "r"(lw[7]));
    }
    __syncthreads();

    float4 acc[8];
    #pragma unroll
    for (int i = 0; i < 8; i++) acc[i] = make_float4(0,0,0,0);
    const int aRow = wid*16 + (lane & 15);
    const int aXor = aRow & 7, aHalf = lane >> 4;
    const int bRow8 = (lane >> 4)*8 + (lane & 7);
    const int bHalf = (lane >> 3) & 1, bx = lane & 7;
    #pragma unroll
    for (int ks = 0; ks < 2; ks++) {
        uint32_t ah[4], al[4];
        const uint32_t ab = sb + oA + aRow*128;
        ldsm_x4(ah, ab + (((2*ks + aHalf) ^ aXor) << 4));
        ldsm_x4(al, ab + (((4 + 2*ks + aHalf) ^ aXor) << 4));
        #pragma unroll
        for (int p = 0; p < 4; p++) {
            const uint32_t rbase = sb + oB + (p*16 + bRow8)*128;
            uint32_t bh[4], bl[4];
            ldsm_x4(bh, rbase + (((2*ks + bHalf) ^ bx) << 4));
            ldsm_x4(bl, rbase + (((4 + 2*ks + bHalf) ^ bx) << 4));
            mma16816(acc[2*p],   ah, bh);     mma16816(acc[2*p],   al, bh);
            mma16816(acc[2*p],   ah, bl);
            mma16816(acc[2*p+1], ah, bh + 2); mma16816(acc[2*p+1], al, bh + 2);
            mma16816(acc[2*p+1], ah, bl + 2);
        }
    }

    __syncthreads();
    float* so = reinterpret_cast<float*>(smp);
    {
        const int row = wid*16 + (lane >> 2);
        const int col = 2*(lane & 3);
        #pragma unroll
        for (int nb = 0; nb < 8; nb++) {
            so[row*64 + nb*8 + col]       = acc[nb].x;
            so[row*64 + nb*8 + col + 1]   = acc[nb].y;
            so[(row+8)*64 + nb*8 + col]   = acc[nb].z;
            so[(row+8)*64 + nb*8 + col+1] = acc[nb].w;
        }
    }
    __syncthreads();
    for (int g = tid; g < 32*8; g += 256) {
        int pp_l = g >> 3, cg = g & 7;
        int pp = ppb + pp_l;
        if (pp >= NPX) continue;
        int co0 = cg*8;
        float v[8];
        #pragma unroll
        for (int j = 0; j < 8; j++) v[j] = -1e30f;
        #pragma unroll
        for (int q = 0; q < 4; q++) {
            const float* rp = &so[(4*pp_l + q)*64 + co0];
            #pragma unroll
            for (int j = 0; j < 8; j++) v[j] = fmaxf(v[j], rp[j]);
        }
        unsigned short hh[8], ll[8];
        #pragma unroll
        for (int j = 0; j < 8; j++) {
            float t = fmaxf(v[j] + bias[co0 + j], 0.f);
            bf16 h = __float2bfloat16(t);
            hh[j] = __bfloat16_as_ushort(h);
            ll[j] = __bfloat16_as_ushort(__float2bfloat16(t - __bfloat162float(h)));
        }
        size_t base = (((size_t)img*HPO + pp/WPO)*WPO + pp%WPO)*64 + co0;
        *reinterpret_cast<uint4*>(outh + base) =
            make_uint4(hh[0]|((uint32_t)hh[1]<<16), hh[2]|((uint32_t)hh[3]<<16),
                       hh[4]|((uint32_t)hh[5]<<16), hh[6]|((uint32_t)hh[7]<<16));
        *reinterpret_cast<uint4*>(outl + base) =
            make_uint4(ll[0]|((uint32_t)ll[1]<<16), ll[2]|((uint32_t)ll[3]<<16),
                       ll[4]|((uint32_t)ll[5]<<16), ll[6]|((uint32_t)ll[7]<<16));
    }
}

// ---------- HMMA conv, pixels-on-M (L2, L3): CIN=64 ----------
// NT threads, MP pooled px per block (M = 4*MP conv rows = (NT/32)*16).
template<int COUT, int HIN, int WIN, int HPO, int WPO, int NROWS, int PW, int NT, int MP>
__global__ void __launch_bounds__(NT)
conv_mma_px(const bf16* __restrict__ inh, const bf16* __restrict__ inl,
            const bf16* __restrict__ wh,  const bf16* __restrict__ wl,
            const float* __restrict__ bias,
            bf16* __restrict__ outh, bf16* __restrict__ outl)
{
    constexpr int NB = COUT/8;
    constexpr int NPAIR = NB/2;
    constexpr int BANDPX = NROWS*PW;
    constexpr uint32_t BH = BANDPX*128;
    constexpr uint32_t CB = COUT*128;
    constexpr uint32_t oB = 2*BH;

    extern __shared__ char dsm[];
    char* smp = (char*)(((uintptr_t)dsm + 1023) & ~(uintptr_t)1023);
    const uint32_t sb = smem_u32(smp);
    const int tid = threadIdx.x, wid = tid >> 5, lane = tid & 31;
    const int img = blockIdx.z, ppb = blockIdx.x * MP;
    const int r0 = ppb / WPO;
    const int ystart = 2*r0 - 1;

    const bf16* ih = inh + (size_t)img * HIN * WIN * 64;
    const bf16* il = inl + (size_t)img * HIN * WIN * 64;

    for (int g = tid; g < BANDPX*8; g += NT) {
        int p = g >> 3, seg = g & 7;
        int row = p / PW, col = p % PW;
        int gy = ystart + row, gx = col - 1;
        bool ok = (gy >= 0 && gy < HIN && gx >= 0 && gx < WIN);
        size_t s = ok ? (((size_t)gy*WIN + gx)*64 + seg*8) : 0;
        uint32_t d = p*128 + ((seg ^ (p & 7)) << 4);
        cpa16(sb + d,      ih + s, ok ? 16 : 0);
        cpa16(sb + BH + d, il + s, ok ? 16 : 0);
    }
    CPA_COMMIT();
    {
        const uint32_t bb = sb + oB;
        for (int g = tid; g < COUT*8; g += NT) {
            int r = g >> 3, seg = g & 7;
            uint32_t d = bb + r*128 + ((seg ^ (r & 7)) << 4);
            size_t s = (size_t)r*64 + seg*8;
            cpa16(d,      wh + s, 16);
            cpa16(d + CB, wl + s, 16);
        }
        CPA_COMMIT();
    }

    float4 acc[NB];
    #pragma unroll
    for (int i = 0; i < NB; i++) acc[i] = make_float4(0,0,0,0);

    const int aRow = wid*16 + (lane & 15);
    const int appd = aRow >> 2, aq = aRow & 3;
    const int ay = 2*((ppb + appd)/WPO) + (aq >> 1);
    const int ax = 2*((ppb + appd)%WPO) + (aq & 1);
    const int p00 = (ay - 2*r0)*PW + ax;
    const int aHalf = lane >> 4;
    const int bRow8 = (lane >> 4)*8 + (lane & 7);
    const int bHalf = (lane >> 3) & 1, bx = lane & 7;

    for (int k = 0; k < 9; k++) {
        CPA_WAIT0();
        __syncthreads();
        if (k < 8) {
            const uint32_t bb = sb + oB + ((k+1) & 1)*(2*CB);
            for (int g = tid; g < COUT*8; g += NT) {
                int r = g >> 3, seg = g & 7;
                uint32_t d = bb + r*128 + ((seg ^ (r & 7)) << 4);
                size_t s = ((size_t)(k+1)*COUT + r)*64 + seg*8;
                cpa16(d,      wh + s, 16);
                cpa16(d + CB, wl + s, 16);
            }
            CPA_COMMIT();
        }
        const int pA = p00 + (k/3)*PW + (k%3);
        const uint32_t aBaseH = sb + pA*128;
        const uint32_t aBaseL = sb + BH + pA*128;
        const int aXor = pA & 7;
        const uint32_t bb = sb + oB + (k & 1)*(2*CB);
        #pragma unroll
        for (int ks = 0; ks < 4; ks++) {
            uint32_t ah[4], al[4];
            const uint32_t ao = (uint32_t)(((2*ks + aHalf) ^ aXor) << 4);
            ldsm_x4(ah, aBaseH + ao);
            ldsm_x4(al, aBaseL + ao);
            #pragma unroll
            for (int p = 0; p < NPAIR; p++) {
                const uint32_t rbase = bb + (p*16 + bRow8)*128 + (((2*ks + bHalf) ^ bx) << 4);
                uint32_t bh[4], bl[4];
                ldsm_x4(bh, rbase);
                ldsm_x4(bl, rbase + CB);
                mma16816(acc[2*p],   ah, bh);     mma16816(acc[2*p],   al, bh);
                mma16816(acc[2*p],   ah, bl);
                mma16816(acc[2*p+1], ah, bh + 2); mma16816(acc[2*p+1], al, bh + 2);
                mma16816(acc[2*p+1], ah, bl + 2);
            }
        }
    }

    __syncthreads();
    float* so = reinterpret_cast<float*>(smp);
    {
        const int row = wid*16 + (lane >> 2);
        const int col = 2*(lane & 3);
        #pragma unroll
        for (int nb = 0; nb < NB; nb++) {
            so[row*COUT + nb*8 + col]       = acc[nb].x;
            so[row*COUT + nb*8 + col + 1]   = acc[nb].y;
            so[(row+8)*COUT + nb*8 + col]   = acc[nb].z;
            so[(row+8)*COUT + nb*8 + col+1] = acc[nb].w;
        }
    }
    __syncthreads();
    for (int g = tid; g < MP*NB; g += NT) {
        int pp_l = g / NB, cg = g % NB;
        int pp = ppb + pp_l;
        if (pp >= HPO*WPO) continue;
        int co0 = cg*8;
        float v[8];
        #pragma unroll
        for (int j = 0; j < 8; j++) v[j] = -1e30f;
        #pragma unroll
        for (int q = 0; q < 4; q++) {
            const float* rp = &so[(4*pp_l + q)*COUT + co0];
            #pragma unroll
            for (int j = 0; j < 8; j++) v[j] = fmaxf(v[j], rp[j]);
        }
        unsigned short hh[8], ll[8];
        #pragma unroll
        for (int j = 0; j < 8; j++) {
            float t = fmaxf(v[j] + bias[co0 + j], 0.f);
            bf16 h = __float2bfloat16(t);
            hh[j] = __bfloat16_as_ushort(h);
            ll[j] = __bfloat16_as_ushort(__float2bfloat16(t - __bfloat162float(h)));
        }
        size_t base = (((size_t)img*HPO + pp/WPO)*WPO + pp%WPO)*COUT + co0;
        *reinterpret_cast<uint4*>(outh + base) =
            make_uint4(hh[0]|((uint32_t)hh[1]<<16), hh[2]|((uint32_t)hh[3]<<16),
                       hh[4]|((uint32_t)hh[5]<<16), hh[6]|((uint32_t)hh[7]<<16));
        *reinterpret_cast<uint4*>(outl + base) =
            make_uint4(ll[0]|((uint32_t)ll[1]<<16), ll[2]|((uint32_t)ll[3]<<16),
                       ll[4]|((uint32_t)ll[5]<<16), ll[6]|((uint32_t)ll[7]<<16));
    }
}

// ---------- HMMA conv, co-on-M (L4) ----------
__global__ void __launch_bounds__(256)
conv_mma_co(const bf16* __restrict__ inh, const bf16* __restrict__ inl,
            const bf16* __restrict__ wh,  const bf16* __restrict__ wl,
            const float* __restrict__ bias, float* __restrict__ outf)
{
    constexpr int NB = 13;
    constexpr uint32_t PXB = 180*256;
    constexpr uint32_t oPxL = PXB, oA = 2*PXB;

    extern __shared__ char dsm[];
    char* smp = (char*)(((uintptr_t)dsm + 1023) & ~(uintptr_t)1023);
    const uint32_t sb = smem_u32(smp);
    const int tid = threadIdx.x, wid = tid >> 5, lane = tid & 31;
    const int img = blockIdx.z, cob = blockIdx.y * 128;

    const bf16* ih = inh + (size_t)img * 100 * 128;
    const bf16* il = inl + (size_t)img * 100 * 128;

    for (int g = tid; g < 180*16; g += 256) {
        int p = g >> 4, seg = g & 15;
        int row = p / 12, col = p % 12;
        int gy = row - 1, gx = col - 1;
        bool ok = (gy >= 0 && gy < 10 && gx >= 0 && gx < 10);
        size_t s = ok ? ((size_t)(gy*10 + gx)*128 + seg*8) : 0;
        uint32_t d = p*256 + ((seg ^ (p & 7)) << 4);
        cpa16(sb + d,        ih + s, ok ? 16 : 0);
        cpa16(sb + oPxL + d, il + s, ok ? 16 : 0);
    }
    CPA_COMMIT();
    {
        const uint32_t ab = sb + oA;
        for (int g = tid; g < 1024; g += 256) {
            int m = g >> 3, seg = g & 7;
            size_t s = ((size_t)cob + m)*64 + seg*8;
            uint32_t d = ab + m*128 + ((seg ^ (m & 7)) << 4);
            cpa16(d,         wh + s, 16);
            cpa16(d + 16384, wl + s, 16);
        }
        CPA_COMMIT();
    }

    float4 acc[NB];
    #pragma unroll
    for (int i = 0; i < NB; i++) acc[i] = make_float4(0,0,0,0);

    const int aRow = wid*16 + (lane & 15);
    const int aXor = aRow & 7, aHalf = lane >> 4;
    const int bHalf = (lane >> 3) & 1;
    // per-lane pixel-row indices for x4 pairs (p<6) and the final x2 (p=6)
    int pb0[7];
    #pragma unroll
    for (int p = 0; p < 7; p++) {
        int n = (p < 6) ? (p*16 + (lane >> 4)*8 + (lane & 7)) : (96 + (lane & 7));
        int pp = n >> 2, q = n & 3;
        if (pp < 25) {
            int y = 2*(pp/5) + (q >> 1);
            int x = 2*(pp%5) + (q & 1);
            pb0[p] = (y + 1)*12 + (x + 1);
        } else pb0[p] = 156;
    }

    for (int it = 0; it < 18; it++) {
        CPA_WAIT0();
        __syncthreads();
        if (it < 17) {
            int kn = (it+1) >> 1, cn = (it+1) & 1;
            const uint32_t ab = sb + oA + ((it+1) & 1)*32768;
            for (int g = tid; g < 1024; g += 256) {
                int m = g >> 3, seg = g & 7;
                size_t s = ((size_t)(kn*2 + cn)*512 + cob + m)*64 + seg*8;
                uint32_t d = ab + m*128 + ((seg ^ (m & 7)) << 4);
                cpa16(d,         wh + s, 16);
                cpa16(d + 16384, wl + s, 16);
            }
            CPA_COMMIT();
        }
        const int k = it >> 1, cic = it & 1;
        const int dtap = (k/3 - 1)*12 + (k%3 - 1);
        const uint32_t aBase = sb + oA + (it & 1)*32768 + aRow*128;
        #pragma unroll
        for (int ks = 0; ks < 4; ks++) {
            uint32_t ah[4], al[4];
            const uint32_t ao = (uint32_t)(((2*ks + aHalf) ^ aXor) << 4);
            ldsm_x4(ah, aBase + ao);
            ldsm_x4(al, aBase + 16384 + ao);
            #pragma unroll
            for (int p = 0; p < 6; p++) {
                const int pb = pb0[p] + dtap;
                const uint32_t bo = sb + pb*256 + ((((cic<<3) + 2*ks + bHalf) ^ (pb & 7)) << 4);
                uint32_t bh[4], bl[4];
                ldsm_x4(bh, bo);
                ldsm_x4(bl, bo + oPxL);
                mma16816(acc[2*p],   ah, bh);     mma16816(acc[2*p],   al, bh);
                mma16816(acc[2*p],   ah, bl);
                mma16816(acc[2*p+1], ah, bh + 2); mma16816(acc[2*p+1], al, bh + 2);
                mma16816(acc[2*p+1], ah, bl + 2);
            }
            {
                const int pb = pb0[6] + dtap;
                const uint32_t bo = sb + pb*256 + ((((cic<<3) + 2*ks + bHalf) ^ (pb & 7)) << 4);
                uint32_t bh[2], bl[2];
                ldsm_x2(bh, bo);
                ldsm_x2(bl, bo + oPxL);
                mma16816(acc[12], ah, bh);
                mma16816(acc[12], al, bh);
                mma16816(acc[12], ah, bl);
            }
        }
    }

    __syncthreads();
    float* so = reinterpret_cast<float*>(smp + oA);
    {
        const int row = wid*16 + (lane >> 2);
        const int col = 2*(lane & 3);
        #pragma unroll
        for (int nb = 0; nb < NB; nb++) {
            so[row*104 + nb*8 + col]       = acc[nb].x;
            so[row*104 + nb*8 + col + 1]   = acc[nb].y;
            so[(row+8)*104 + nb*8 + col]   = acc[nb].z;
            so[(row+8)*104 + nb*8 + col+1] = acc[nb].w;
        }
    }
    __syncthreads();
    for (int g = tid; g < 3200; g += 256) {
        int co_l = g / 25, pp = g % 25;
        float4 q4 = *reinterpret_cast<float4*>(&so[co_l*104 + 4*pp]);
        float v = fmaxf(fmaxf(q4.x, q4.y), fmaxf(q4.z, q4.w));
        v = fmaxf(v + bias[cob + co_l], 0.f);
        outf[((size_t)img*512 + cob + co_l)*25 + pp] = v;
    }
}

// ---------- prototypes / head / scores ----------
__global__ void proto_kernel(const float* __restrict__ ytr) {
    const int bk = blockIdx.x, b = bk/5, k = bk - b*5, c = threadIdx.x;
    float ssum = 0.f, ysum = 0.f;
    for (int n = 0; n < 25; n++) {
        float y = ytr[(b*25 + n)*5 + k];
        ysum += y;
        if (y != 0.f) {
            const float* fp = &g_f4[((size_t)(b*25 + n)*512 + c)*25];
            float sp = 0.f;
            #pragma unroll
            for (int p = 0; p < 25; p++) sp += fp[p];
            ssum = fmaf(y, sp, ssum);
        }
    }
    float val = ssum / (ysum * 25.f);
    __shared__ float red[512];
    red[c] = val*val; __syncthreads();
    for (int o = 256; o > 0; o >>= 1) { if (c < o) red[c] += red[c+o]; __syncthreads(); }
    g_fa[(size_t)bk*512 + c] = val / fmaxf(sqrtf(red[0]), 1e-12f);
}
__global__ void predict_kernel(const float* __restrict__ wc, const float* __restrict__ bc,
                               float* __restrict__ out) {
    const int q = blockIdx.x, c = threadIdx.x;
    const float* fp = &g_f4[((size_t)(100 + q)*512 + c)*25];
    float s = 0.f;
    #pragma unroll
    for (int p = 0; p < 25; p++) s += fp[p];
    s /= 25.f;
    __shared__ float red[512], sf[512];
    red[c] = s*s; __syncthreads();
    for (int o = 256; o > 0; o >>= 1) { if (c < o) red[c] += red[c+o]; __syncthreads(); }
    sf[c] = s / fmaxf(sqrtf(red[0]), 1e-12f);
    __syncthreads();
    if (c < 64) {
        float a = bc[c];
        const float* wr = &wc[(size_t)c*512];
        #pragma unroll 8
        for (int d = 0; d < 512; d++) a = fmaf(sf[d], wr[d], a);
        out[(size_t)q*64 + c] = a;
    }
}
__global__ void score_kernel(float* __restrict__ out) {
    constexpr int CH = 128;
    __shared__ float sf[CH*25], sfa[5*129], snrm[25];
    const int q = blockIdx.x, b = q/75, tid = threadIdx.x;
    const float* fbase = &g_f4[(size_t)(100 + q)*512*25];
    float acc = 0.f;
    const int di = tid/25, dp = tid%25, pn = tid - 125;
    for (int cb = 0; cb < 4; cb++) {
        __syncthreads();
        for (int i = tid; i < CH*25; i += 256) sf[i] = fbase[cb*CH*25 + i];
        for (int i = tid; i < 5*CH; i += 256) {
            int ii = i/CH, cc = i - ii*CH;
            sfa[ii*129 + cc] = g_fa[((size_t)(b*5 + ii))*512 + cb*CH + cc];
        }
        __syncthreads();
        if (tid < 125) {
            #pragma unroll 4
            for (int c = 0; c < CH; c++) acc = fmaf(sf[c*25 + dp], sfa[di*129 + c], acc);
        } else if (tid < 150) {
            #pragma unroll 4
            for (int c = 0; c < CH; c++) { float v = sf[c*25 + pn]; acc = fmaf(v, v, acc); }
        }
    }
    if (tid >= 125 && tid < 150) snrm[pn] = fmaxf(sqrtf(acc), 1e-12f);
    __syncthreads();
    if (tid < 125) out[(size_t)q*125 + tid] = acc / snrm[dp];
}

// ---------- launch ----------
extern "C" void kernel_launch(void* const* d_in, const int* in_sizes, int n_in,
                              void* d_out, int out_size)
{
    const float* xtr = (const float*)d_in[0];
    const float* xte = (const float*)d_in[1];
    const float* ytr = (const float*)d_in[2];
    const float* w1 = (const float*)d_in[4];  const float* b1 = (const float*)d_in[5];
    const float* w2 = (const float*)d_in[6];  const float* b2 = (const float*)d_in[7];
    const float* w3 = (const float*)d_in[8];  const float* b3 = (const float*)d_in[9];
    const float* w4 = (const float*)d_in[10]; const float* b4 = (const float*)d_in[11];
    const float* wc = (const float*)d_in[12]; const float* bc = (const float*)d_in[13];
    float* out = (float*)d_out;

    float *f4;
    bf16 *a1h,*a1l,*a2h,*a2l,*a3h,*a3l,*w1q,*w2h,*w2l,*w3h,*w3l,*w4h,*w4l;
    cudaGetSymbolAddress((void**)&f4, g_f4);
    cudaGetSymbolAddress((void**)&w1q, g_w1q);
    cudaGetSymbolAddress((void**)&a1h, g_a1h); cudaGetSymbolAddress((void**)&a1l, g_a1l);
    cudaGetSymbolAddress((void**)&a2h, g_a2h); cudaGetSymbolAddress((void**)&a2l, g_a2l);
    cudaGetSymbolAddress((void**)&a3h, g_a3h); cudaGetSymbolAddress((void**)&a3l, g_a3l);
    cudaGetSymbolAddress((void**)&w2h, g_w2h); cudaGetSymbolAddress((void**)&w2l, g_w2l);
    cudaGetSymbolAddress((void**)&w3h, g_w3h); cudaGetSymbolAddress((void**)&w3l, g_w3l);
    cudaGetSymbolAddress((void**)&w4h, g_w4h); cudaGetSymbolAddress((void**)&w4l, g_w4l);

    repack_w1_kernel<<<8, 256>>>(w1, w1q);
    repack_bf16_kernel<<<144, 256>>>(w2, w2h, w2l, 64, 64);
    repack_bf16_kernel<<<288, 256>>>(w3, w3h, w3l, 64, 128);
    repack_bf16_kernel<<<2304, 256>>>(w4, w4h, w4l, 128, 512);

    {   // L1 HMMA: 56 px-tiles x 400 imgs
        int sm = 33792;
        cudaFuncSetAttribute(conv1_mma, cudaFuncAttributeMaxDynamicSharedMemorySize, sm);
        conv1_mma<<<dim3(56, 1, 400), 256, sm>>>(xtr, xte, 100, w1q, b1, a1h, a1l);
    }
    {   // L2: 64->64, 512 threads, 64 pooled px/block, band 10x44
        auto kfn = conv_mma_px<64, 42, 42, 21, 21, 10, 44, 512, 64>;
        int sm = 1024 + 2*(10*44*128) + 4*(64*128);
        cudaFuncSetAttribute(kfn, cudaFuncAttributeMaxDynamicSharedMemorySize, sm);
        kfn<<<dim3(7, 1, 400), 512, sm>>>(a1h, a1l, w2h, w2l, b2, a2h, a2l);
    }
    {   // L3: 64->128, 512 threads, 64 pooled px/block, band 16x28
        auto kfn = conv_mma_px<128, 21, 21, 10, 10, 16, 28, 512, 64>;
        int sm = 1024 + 2*(16*28*128) + 4*(128*128);
        cudaFuncSetAttribute(kfn, cudaFuncAttributeMaxDynamicSharedMemorySize, sm);
        kfn<<<dim3(2, 1, 400), 512, sm>>>(a2h, a2l, w3h, w3l, b3, a3h, a3l);
    }
    {   // L4: 128->512
        int sm = 1024 + 2*(180*256) + 2*32768;
        cudaFuncSetAttribute(conv_mma_co, cudaFuncAttributeMaxDynamicSharedMemorySize, sm);
        conv_mma_co<<<dim3(1, 4, 400), 256, sm>>>(a3h, a3l, w4h, w4l, b4, f4);
    }

    proto_kernel<<<20, 512>>>(ytr);
    predict_kernel<<<300, 512>>>(wc, bc, out);
    score_kernel<<<300, 256>>>(out + 300*64);
}